// round 1
// baseline (speedup 1.0000x reference)
#include <cuda_runtime.h>
#include <cstdint>

// ---------------------------------------------------------------------------
// Problem constants
// ---------------------------------------------------------------------------
#define T_STEPS 16
#define NB      32
#define CCH     128
#define HH      32
#define WW      32
#define COUT    128
#define HW      (HH*WW)                 // 1024
#define ELEMS_T (NB*CCH*HH*WW)          // 4,194,304 elements per timestep
#define IMGS    (T_STEPS*NB)            // 512
#define SP_IMG  (CCH*HW)                // 131072 bytes (uint8) per image

// Scratch: spikes as uint8, [img][c][hw]
__device__ unsigned char g_spikes[(size_t)T_STEPS * ELEMS_T];

// ---------------------------------------------------------------------------
// Kernel 1: LIF scan (elementwise over N*C*H*W, sequential over T)
//   v <- v + (x_t - v)*0.5 ; s = (v >= 1) ; v <- 0 if s
// Vectorized: 4 elements / thread.
// ---------------------------------------------------------------------------
__global__ __launch_bounds__(256) void lif_kernel(const float* __restrict__ x)
{
    int i = (blockIdx.x * 256 + threadIdx.x) * 4;   // 0 .. ELEMS_T-4
    if (i >= ELEMS_T) return;
    float v0 = 0.f, v1 = 0.f, v2 = 0.f, v3 = 0.f;
#pragma unroll
    for (int t = 0; t < T_STEPS; t++) {
        float4 xv = *reinterpret_cast<const float4*>(x + (size_t)t * ELEMS_T + i);
        // Match reference rounding: v = v + (x - v)*0.5
        v0 = v0 + (xv.x - v0) * 0.5f;
        v1 = v1 + (xv.y - v1) * 0.5f;
        v2 = v2 + (xv.z - v2) * 0.5f;
        v3 = v3 + (xv.w - v3) * 0.5f;
        uchar4 s;
        s.x = (v0 >= 1.0f);  if (v0 >= 1.0f) v0 = 0.f;
        s.y = (v1 >= 1.0f);  if (v1 >= 1.0f) v1 = 0.f;
        s.z = (v2 >= 1.0f);  if (v2 >= 1.0f) v2 = 0.f;
        s.w = (v3 >= 1.0f);  if (v3 >= 1.0f) v3 = 0.f;
        *reinterpret_cast<uchar4*>(g_spikes + (size_t)t * ELEMS_T + i) = s;
    }
}

// ---------------------------------------------------------------------------
// Packed fp32x2 FMA helpers (FFMA2: 2x FMA throughput vs 3-reg FFMA on B300)
// ---------------------------------------------------------------------------
__device__ __forceinline__ unsigned long long pack2(float x)
{
    unsigned long long r;
    asm("mov.b64 %0, {%1, %1};" : "=l"(r) : "f"(x));
    return r;
}
__device__ __forceinline__ void ffma2(unsigned long long& d,
                                      unsigned long long a,
                                      unsigned long long b)
{
    asm("fma.rn.f32x2 %0, %1, %2, %0;" : "+l"(d) : "l"(a), "l"(b));
}

// ---------------------------------------------------------------------------
// Kernel 2: fused depthwise3x3 + pointwise1x1 + BatchNorm
// Block = one image x 4-row pixel tile (128 pixels). Grid (8, 512).
// SMEM: spike tile (halo'ed, uint8), dw weights, pw chunk (BN-scaled,
// transposed), staged dw outputs. GEMM: 128(o) x 128(p) x 128(c),
// k-chunked by 32, 8x8 register tile per thread, FFMA2.
// ---------------------------------------------------------------------------
// Shared layout (bytes):
//   s_sp   : 128 ch * 6 rows * 48 pitch      = 36864   (uint8; data at byte 4..35, halo 3 & 36)
//   s_dww  : 1152 f
//   s_dwb  : 128 f
//   s_scale: 128 f
//   s_bias : 128 f
//   s_pwT  : 32*129 = 4128 f
//   s_dws  : 32*128 = 4096 f
#define SP_PITCH 48
#define SP_CH    (6 * SP_PITCH)   // 288
#define SMEM_F_OFF 36864
#define SMEM_BYTES (SMEM_F_OFF + 4 * (1152 + 128 + 128 + 128 + 4128 + 4096))

__global__ __launch_bounds__(256, 2) void fused_conv_kernel(
    const float* __restrict__ dw_w,  const float* __restrict__ dw_b,
    const float* __restrict__ pw_w,  const float* __restrict__ pw_b,
    const float* __restrict__ gamma, const float* __restrict__ beta,
    const float* __restrict__ rmean, const float* __restrict__ rvar,
    float* __restrict__ out)
{
    extern __shared__ unsigned char smem[];
    unsigned char* s_sp  = smem;
    float* s_dww   = reinterpret_cast<float*>(smem + SMEM_F_OFF);
    float* s_dwb   = s_dww + 1152;
    float* s_scale = s_dwb + 128;
    float* s_bias  = s_scale + 128;
    float* s_pwT   = s_bias + 128;          // [32][129]
    float* s_dws   = s_pwT + 32 * 129;      // [32][128]

    const int tid   = threadIdx.x;
    const int ptile = blockIdx.x;           // 0..7 (4 rows each)
    const int img   = blockIdx.y;           // 0..511
    const int row0  = ptile * 4;

    // ---- zero spike tile (incl. halo) ----
    {
        uint4 z = make_uint4(0u, 0u, 0u, 0u);
        uint4* sp4 = reinterpret_cast<uint4*>(s_sp);
        #pragma unroll
        for (int i = tid; i < 36864 / 16; i += 256) sp4[i] = z;
    }
    // ---- weights / BN folding ----
    for (int i = tid; i < 1152; i += 256) s_dww[i] = dw_w[i];
    if (tid < 128) {
        s_dwb[tid] = dw_b[tid];
        float sc = gamma[tid] * rsqrtf(rvar[tid] + 1e-5f);
        s_scale[tid] = sc;
        s_bias[tid]  = (pw_b[tid] - rmean[tid]) * sc + beta[tid];
    }
    __syncthreads();

    // ---- load spike tile rows (row0-1 .. row0+4), 128 channels ----
    {
        const unsigned char* gsp = g_spikes + (size_t)img * SP_IMG;
        for (int ridx = tid; ridx < 768; ridx += 256) {
            int c  = ridx / 6;
            int rl = ridx - c * 6;
            int gr = row0 - 1 + rl;
            if ((unsigned)gr < 32u) {
                const uint4* src = reinterpret_cast<const uint4*>(gsp + c * 1024 + gr * 32);
                uint4 a = src[0], b = src[1];
                uint32_t* dst = reinterpret_cast<uint32_t*>(s_sp + c * SP_CH + rl * SP_PITCH + 4);
                dst[0] = a.x; dst[1] = a.y; dst[2] = a.z; dst[3] = a.w;
                dst[4] = b.x; dst[5] = b.y; dst[6] = b.z; dst[7] = b.w;
            }
        }
    }
    __syncthreads();

    const int tx = tid & 15;     // pixel group: p0 = tx*8
    const int ty = tid >> 4;     // out-ch group: o0 = ty*8

    unsigned long long acc[8][4];
    #pragma unroll
    for (int i = 0; i < 8; i++)
        #pragma unroll
        for (int j = 0; j < 4; j++) acc[i][j] = 0ull;

    for (int kc = 0; kc < 4; kc++) {
        // -- stage BN-scaled, transposed pw chunk: s_pwT[k][o] --
        #pragma unroll
        for (int i2 = 0; i2 < 16; i2++) {
            int idx = tid + i2 * 256;            // 0..4095
            int cl = idx & 31, o = idx >> 5;
            s_pwT[cl * 129 + o] = pw_w[o * 128 + kc * 32 + cl] * s_scale[o];
        }
        // -- compute depthwise outputs into s_dws[k][p] --
        #pragma unroll
        for (int i2 = 0; i2 < 16; i2++) {
            int idx = tid + i2 * 256;            // 0..4095
            int k = idx >> 7, p = idx & 127;
            int c = kc * 32 + k;
            int r = p >> 5, col = p & 31;
            const unsigned char* spb = s_sp + c * SP_CH + r * SP_PITCH + col + 3;
            const float* w = s_dww + c * 9;
            float a = s_dwb[c];
            #pragma unroll
            for (int ii = 0; ii < 3; ii++)
                #pragma unroll
                for (int jj = 0; jj < 3; jj++)
                    a += w[ii * 3 + jj] * (float)spb[ii * SP_PITCH + jj];
            s_dws[k * 128 + p] = a;
        }
        __syncthreads();
        // -- GEMM over this k-chunk --
        #pragma unroll 4
        for (int k = 0; k < 32; k++) {
            ulonglong2 b0 = *reinterpret_cast<ulonglong2*>(&s_dws[k * 128 + tx * 8]);
            ulonglong2 b1 = *reinterpret_cast<ulonglong2*>(&s_dws[k * 128 + tx * 8 + 4]);
            const float* arow = &s_pwT[k * 129 + ty * 8];
            #pragma unroll
            for (int i = 0; i < 8; i++) {
                unsigned long long a2 = pack2(arow[i]);
                ffma2(acc[i][0], a2, b0.x);
                ffma2(acc[i][1], a2, b0.y);
                ffma2(acc[i][2], a2, b1.x);
                ffma2(acc[i][3], a2, b1.y);
            }
        }
        __syncthreads();
    }

    // ---- epilogue: add fused bias, write out ----
    float* outp = out + (size_t)img * (COUT * HW) + (ty * 8) * HW + ptile * 128 + tx * 8;
    #pragma unroll
    for (int i = 0; i < 8; i++) {
        float bi = s_bias[ty * 8 + i];
        float2 f0 = *reinterpret_cast<float2*>(&acc[i][0]);
        float2 f1 = *reinterpret_cast<float2*>(&acc[i][1]);
        float2 f2 = *reinterpret_cast<float2*>(&acc[i][2]);
        float2 f3 = *reinterpret_cast<float2*>(&acc[i][3]);
        float4 v0 = make_float4(f0.x + bi, f0.y + bi, f1.x + bi, f1.y + bi);
        float4 v1 = make_float4(f2.x + bi, f2.y + bi, f3.x + bi, f3.y + bi);
        *reinterpret_cast<float4*>(outp + i * HW)     = v0;
        *reinterpret_cast<float4*>(outp + i * HW + 4) = v1;
    }
}

// ---------------------------------------------------------------------------
// Launcher
// ---------------------------------------------------------------------------
extern "C" void kernel_launch(void* const* d_in, const int* in_sizes, int n_in,
                              void* d_out, int out_size)
{
    const float* x     = (const float*)d_in[0];
    const float* dw_w  = (const float*)d_in[1];
    const float* dw_b  = (const float*)d_in[2];
    const float* pw_w  = (const float*)d_in[3];
    const float* pw_b  = (const float*)d_in[4];
    const float* gamma = (const float*)d_in[5];
    const float* beta  = (const float*)d_in[6];
    const float* rmean = (const float*)d_in[7];
    const float* rvar  = (const float*)d_in[8];
    float* out = (float*)d_out;

    // K1: LIF scan -> spikes (uint8 scratch)
    lif_kernel<<<ELEMS_T / (256 * 4), 256>>>(x);

    // K2: fused dw3x3 + pw1x1 + BN
    cudaFuncSetAttribute(fused_conv_kernel,
                         cudaFuncAttributeMaxDynamicSharedMemorySize, SMEM_BYTES);
    dim3 grid(8, IMGS);
    fused_conv_kernel<<<grid, 256, SMEM_BYTES>>>(dw_w, dw_b, pw_w, pw_b,
                                                 gamma, beta, rmean, rvar, out);
}

// round 3
// speedup vs baseline: 2.4143x; 2.4143x over previous
#include <cuda_runtime.h>
#include <cstdint>

// ---------------------------------------------------------------------------
// Problem constants
// ---------------------------------------------------------------------------
#define T_STEPS 16
#define NB      32
#define HH      32
#define WW      32
#define COUT    128
#define HW      (HH*WW)                 // 1024
#define ELEMS_T (NB*128*HH*WW)          // 4,194,304 per timestep
#define IMGS    (T_STEPS*NB)            // 512
#define SP_IMG  (128*HW)                // 131072 bytes per image
#define NTILES  (IMGS*8)                // 4096 pixel tiles of 128 px
#define GRID    152
#define NTHREADS 256

// Scratch: spikes as uint8, [img][c][hw]
__device__ unsigned char g_spikes[(size_t)T_STEPS * ELEMS_T];

// ---------------------------------------------------------------------------
// Kernel 1: LIF scan
// ---------------------------------------------------------------------------
__global__ __launch_bounds__(256) void lif_kernel(const float* __restrict__ x)
{
    int i = (blockIdx.x * 256 + threadIdx.x) * 4;
    if (i >= ELEMS_T) return;
    float v0 = 0.f, v1 = 0.f, v2 = 0.f, v3 = 0.f;
#pragma unroll
    for (int t = 0; t < T_STEPS; t++) {
        float4 xv = *reinterpret_cast<const float4*>(x + (size_t)t * ELEMS_T + i);
        v0 = v0 + (xv.x - v0) * 0.5f;
        v1 = v1 + (xv.y - v1) * 0.5f;
        v2 = v2 + (xv.z - v2) * 0.5f;
        v3 = v3 + (xv.w - v3) * 0.5f;
        uchar4 s;
        s.x = (v0 >= 1.0f);  if (v0 >= 1.0f) v0 = 0.f;
        s.y = (v1 >= 1.0f);  if (v1 >= 1.0f) v1 = 0.f;
        s.z = (v2 >= 1.0f);  if (v2 >= 1.0f) v2 = 0.f;
        s.w = (v3 >= 1.0f);  if (v3 >= 1.0f) v3 = 0.f;
        *reinterpret_cast<uchar4*>(g_spikes + (size_t)t * ELEMS_T + i) = s;
    }
}

// ---------------------------------------------------------------------------
// tf32 helpers (portable PTX; no sm_103a-only features)
// ---------------------------------------------------------------------------
__device__ __forceinline__ uint32_t cvt_tf32(float f) {
    uint32_t r;
    asm("cvt.rna.tf32.f32 %0, %1;" : "=r"(r) : "f"(f));
    return r;
}
__device__ __forceinline__ void mma_tf32(float& c0, float& c1, float& c2, float& c3,
                                         uint32_t a0, uint32_t a1, uint32_t a2, uint32_t a3,
                                         uint32_t b0, uint32_t b1)
{
    asm volatile(
        "mma.sync.aligned.m16n8k8.row.col.f32.tf32.tf32.f32 "
        "{%0,%1,%2,%3}, {%4,%5,%6,%7}, {%8,%9}, {%0,%1,%2,%3};"
        : "+f"(c0), "+f"(c1), "+f"(c2), "+f"(c3)
        : "r"(a0), "r"(a1), "r"(a2), "r"(a3), "r"(b0), "r"(b1));
}

// ---------------------------------------------------------------------------
// Kernel 2: persistent fused dw3x3 (CUDA cores) + pw1x1+BN (mma.sync tf32)
//
// SMEM (bytes):
//   0      : s_bias [128] f32
//   512    : s_dww  [1152] f32
//   5120   : s_sp   spike tile, 128 ch * 304 B (6 rows * 48B pitch + pad)
//   44032  : s_B    128(k) x 132-stride (n) tf32 words (dw outputs)
// ---------------------------------------------------------------------------
#define OFF_BIAS  0
#define OFF_DWW   512
#define OFF_SP    5120
#define SP_CH     304
#define OFF_B     44032
#define BSTRIDE   132
#define SMEM_TOTAL (OFF_B + 128*BSTRIDE*4)   // 111616

__device__ __forceinline__ void load_spikes(unsigned char* s_sp, int t, int tid)
{
    int img  = t >> 3;
    int row0 = (t & 7) * 4;
    const unsigned char* gsp = g_spikes + (size_t)img * SP_IMG;
    int cc = tid & 127, rb = tid >> 7;
#pragma unroll
    for (int j = 0; j < 3; j++) {
        int rl = rb + j * 2;                 // 0..5
        int gr = row0 - 1 + rl;
        uint32_t* dst = reinterpret_cast<uint32_t*>(s_sp + cc * SP_CH + rl * 48 + 4);
        if ((unsigned)gr < 32u) {
            const uint4* src = reinterpret_cast<const uint4*>(gsp + cc * 1024 + gr * 32);
            uint4 a = src[0], b = src[1];
            dst[0] = a.x; dst[1] = a.y; dst[2] = a.z; dst[3] = a.w;
            dst[4] = b.x; dst[5] = b.y; dst[6] = b.z; dst[7] = b.w;
        } else {
#pragma unroll
            for (int k = 0; k < 8; k++) dst[k] = 0u;
        }
    }
}

__global__ __launch_bounds__(NTHREADS, 1) void fused_mma_kernel(
    const float* __restrict__ dw_w,  const float* __restrict__ dw_b,
    const float* __restrict__ pw_w,  const float* __restrict__ pw_b,
    const float* __restrict__ gamma, const float* __restrict__ beta,
    const float* __restrict__ rmean, const float* __restrict__ rvar,
    float* __restrict__ out)
{
    extern __shared__ unsigned char smem[];
    float*    s_bias = reinterpret_cast<float*>(smem + OFF_BIAS);
    float*    s_dww  = reinterpret_cast<float*>(smem + OFF_DWW);
    unsigned char* s_sp = smem + OFF_SP;
    uint32_t* s_B    = reinterpret_cast<uint32_t*>(smem + OFF_B);

    const int tid = threadIdx.x;
    const int wid = tid >> 5;
    const int lid = tid & 31;
    const int g   = lid >> 2;      // groupID (0..7)
    const int t4  = lid & 3;       // threadID_in_group (0..3)
    const int mg  = wid & 3;       // m-group
    const int ng  = wid >> 2;      // n-group
    const int ob  = mg * 32;       // warp out-channel base
    const int nb  = ng * 64;       // warp pixel base

    // ---- one-time setup ----
    {
        uint4 z = make_uint4(0u, 0u, 0u, 0u);
        uint4* p4 = reinterpret_cast<uint4*>(s_sp);
        for (int i = tid; i < (128 * SP_CH) / 16; i += NTHREADS) p4[i] = z;
    }
    for (int i = tid; i < 1152; i += NTHREADS) s_dww[i] = dw_w[i];
    if (tid < 128) {   // fold dw bias + BN shift + pw bias into per-o bias
        int o = tid;
        float sc = gamma[o] * rsqrtf(rvar[o] + 1e-5f);
        float s = 0.f;
        for (int c = 0; c < 128; c++) s += pw_w[o * 128 + c] * dw_b[c];
        s_bias[o] = beta[o] + sc * (pw_b[o] - rmean[o] + s);
    }

    // ---- preload A fragments (BN-scaled pw weights, tf32) : constant across tiles ----
    uint32_t af[16][2][4];
#pragma unroll
    for (int mt = 0; mt < 2; mt++) {
        int o0 = ob + mt * 16 + g;
        int o1 = o0 + 8;
        float s0 = gamma[o0] * rsqrtf(rvar[o0] + 1e-5f);
        float s1 = gamma[o1] * rsqrtf(rvar[o1] + 1e-5f);
        const float* w0 = pw_w + o0 * 128 + t4;
        const float* w1 = pw_w + o1 * 128 + t4;
#pragma unroll
        for (int ks = 0; ks < 16; ks++) {
            af[ks][mt][0] = cvt_tf32(w0[ks * 8]     * s0);
            af[ks][mt][1] = cvt_tf32(w1[ks * 8]     * s1);
            af[ks][mt][2] = cvt_tf32(w0[ks * 8 + 4] * s0);
            af[ks][mt][3] = cvt_tf32(w1[ks * 8 + 4] * s1);
        }
    }

    __syncthreads();

    // ---- per-thread constants for dw stage ----
    const int c  = tid & 127;            // channel
    const int rp = tid >> 7;             // row-pair selector
    float w[9];
#pragma unroll
    for (int i = 0; i < 9; i++) w[i] = s_dww[c * 9 + i];
    const unsigned char* sprow = s_sp + c * SP_CH;
    uint32_t* bst = s_B + c * BSTRIDE + rp * 64;

    // B fragment lane base pointer: row k = t4, col n = nb + g
    const uint32_t* bld = s_B + t4 * BSTRIDE + nb + g;

    const float bias00 = s_bias[ob + g];
    const float bias01 = s_bias[ob + g + 8];
    const float bias10 = s_bias[ob + 16 + g];
    const float bias11 = s_bias[ob + 24 + g];

    // preload first tile
    int t = blockIdx.x;
    load_spikes(s_sp, t, tid);
    __syncthreads();

    for (; t < NTILES; t += GRID) {
        // ================= depthwise 3x3 =================
        float acc0[32], acc1[32];
#pragma unroll
        for (int i = 0; i < 32; i++) { acc0[i] = 0.f; acc1[i] = 0.f; }
#pragma unroll
        for (int ir = 0; ir < 4; ir++) {
            const uint4* r4 = reinterpret_cast<const uint4*>(sprow + (rp * 2 + ir) * 48);
            uint4 ua = r4[0], ub = r4[1], uc = r4[2];
            uint32_t uu[12] = {ua.x, ua.y, ua.z, ua.w, ub.x, ub.y, ub.z, ub.w,
                               uc.x, uc.y, uc.z, uc.w};
            float f[34];
#pragma unroll
            for (int j = 0; j < 34; j++) {
                int b = j + 3;
                uint32_t v = __byte_perm(uu[b >> 2], 0u, 0x4440u | (uint32_t)(b & 3));
                f[j] = __int_as_float(v * 0x3f800000u);
            }
            if (ir < 3) {
                const int tb = ir * 3;
#pragma unroll
                for (int col = 0; col < 32; col++)
                    acc0[col] += w[tb] * f[col] + w[tb + 1] * f[col + 1] + w[tb + 2] * f[col + 2];
            }
            if (ir > 0) {
                const int tb = (ir - 1) * 3;
#pragma unroll
                for (int col = 0; col < 32; col++)
                    acc1[col] += w[tb] * f[col] + w[tb + 1] * f[col + 1] + w[tb + 2] * f[col + 2];
            }
        }
        // store B [k=c][n], tf32, conflict-free float4 STS
#pragma unroll
        for (int j = 0; j < 8; j++) {
            uint4 v0, v1;
            v0.x = cvt_tf32(acc0[4*j]);   v0.y = cvt_tf32(acc0[4*j+1]);
            v0.z = cvt_tf32(acc0[4*j+2]); v0.w = cvt_tf32(acc0[4*j+3]);
            v1.x = cvt_tf32(acc1[4*j]);   v1.y = cvt_tf32(acc1[4*j+1]);
            v1.z = cvt_tf32(acc1[4*j+2]); v1.w = cvt_tf32(acc1[4*j+3]);
            *reinterpret_cast<uint4*>(bst + 4*j)      = v0;
            *reinterpret_cast<uint4*>(bst + 32 + 4*j) = v1;
        }
        __syncthreads();

        // ================= GEMM: 32o x 64px x 128c per warp =================
        float acc[2][8][4];
#pragma unroll
        for (int mt = 0; mt < 2; mt++)
#pragma unroll
            for (int nt = 0; nt < 8; nt++)
#pragma unroll
                for (int r = 0; r < 4; r++) acc[mt][nt][r] = 0.f;

#pragma unroll
        for (int ks = 0; ks < 16; ks++) {
            const uint32_t* bp = bld + ks * 8 * BSTRIDE;
            uint32_t b0[8], b1[8];
#pragma unroll
            for (int nt = 0; nt < 8; nt++) {
                b0[nt] = bp[nt * 8];
                b1[nt] = bp[nt * 8 + 4 * BSTRIDE];
            }
#pragma unroll
            for (int nt = 0; nt < 8; nt++) {
                mma_tf32(acc[0][nt][0], acc[0][nt][1], acc[0][nt][2], acc[0][nt][3],
                         af[ks][0][0], af[ks][0][1], af[ks][0][2], af[ks][0][3],
                         b0[nt], b1[nt]);
                mma_tf32(acc[1][nt][0], acc[1][nt][1], acc[1][nt][2], acc[1][nt][3],
                         af[ks][1][0], af[ks][1][1], af[ks][1][2], af[ks][1][3],
                         b0[nt], b1[nt]);
            }
        }

        // ---- prefetch next spike tile (LDG latency hides under epilogue) ----
        int tn = t + GRID;
        if (tn < NTILES) load_spikes(s_sp, tn, tid);

        // ================= epilogue: bias + store =================
        {
            const int img = t >> 3, ptile = t & 7;
            float* obase = out + (size_t)img * (COUT * HW) + ptile * 128 + nb + 2 * t4;
#pragma unroll
            for (int mt = 0; mt < 2; mt++) {
                const float blo = (mt == 0) ? bias00 : bias10;
                const float bhi = (mt == 0) ? bias01 : bias11;
                float* r0 = obase + (size_t)(ob + mt * 16 + g) * HW;
#pragma unroll
                for (int nt = 0; nt < 8; nt++) {
                    float2 v0 = make_float2(acc[mt][nt][0] + blo, acc[mt][nt][1] + blo);
                    float2 v1 = make_float2(acc[mt][nt][2] + bhi, acc[mt][nt][3] + bhi);
                    *reinterpret_cast<float2*>(r0 + nt * 8)            = v0;
                    *reinterpret_cast<float2*>(r0 + 8 * HW + nt * 8)   = v1;
                }
            }
        }
        __syncthreads();   // B consumed + next spikes visible before next dw stage
    }
}

// ---------------------------------------------------------------------------
// Launcher
// ---------------------------------------------------------------------------
extern "C" void kernel_launch(void* const* d_in, const int* in_sizes, int n_in,
                              void* d_out, int out_size)
{
    const float* x     = (const float*)d_in[0];
    const float* dw_w  = (const float*)d_in[1];
    const float* dw_b  = (const float*)d_in[2];
    const float* pw_w  = (const float*)d_in[3];
    const float* pw_b  = (const float*)d_in[4];
    const float* gamma = (const float*)d_in[5];
    const float* beta  = (const float*)d_in[6];
    const float* rmean = (const float*)d_in[7];
    const float* rvar  = (const float*)d_in[8];
    float* out = (float*)d_out;

    lif_kernel<<<ELEMS_T / (256 * 4), 256>>>(x);

    cudaFuncSetAttribute(fused_mma_kernel,
                         cudaFuncAttributeMaxDynamicSharedMemorySize, SMEM_TOTAL);
    fused_mma_kernel<<<GRID, NTHREADS, SMEM_TOTAL>>>(dw_w, dw_b, pw_w, pw_b,
                                                     gamma, beta, rmean, rvar, out);
}

// round 4
// speedup vs baseline: 2.8055x; 1.1620x over previous
#include <cuda_runtime.h>
#include <cstdint>

#define T_STEPS 16
#define NB      32
#define HH      32
#define WW      32
#define COUT    128
#define HW      (HH*WW)
#define ELEMS_T (NB*128*HH*WW)
#define IMGS    (T_STEPS*NB)
#define SP_IMG  (128*HW)
#define NTILES  (IMGS*8)
#define GRID    152
#define NTHREADS 256

__device__ unsigned char g_spikes[(size_t)T_STEPS * ELEMS_T];

// ---------------------------------------------------------------------------
// Kernel 1: LIF scan (spikes stored as 0xFF/0x00 for sign-PRMT conversion)
// ---------------------------------------------------------------------------
__global__ __launch_bounds__(256) void lif_kernel(const float* __restrict__ x)
{
    int i = (blockIdx.x * 256 + threadIdx.x) * 4;
    if (i >= ELEMS_T) return;
    float v0 = 0.f, v1 = 0.f, v2 = 0.f, v3 = 0.f;
#pragma unroll
    for (int t = 0; t < T_STEPS; t++) {
        float4 xv = *reinterpret_cast<const float4*>(x + (size_t)t * ELEMS_T + i);
        v0 = v0 + (xv.x - v0) * 0.5f;
        v1 = v1 + (xv.y - v1) * 0.5f;
        v2 = v2 + (xv.z - v2) * 0.5f;
        v3 = v3 + (xv.w - v3) * 0.5f;
        uchar4 s;
        s.x = (v0 >= 1.0f) ? 0xFFu : 0u;  if (v0 >= 1.0f) v0 = 0.f;
        s.y = (v1 >= 1.0f) ? 0xFFu : 0u;  if (v1 >= 1.0f) v1 = 0.f;
        s.z = (v2 >= 1.0f) ? 0xFFu : 0u;  if (v2 >= 1.0f) v2 = 0.f;
        s.w = (v3 >= 1.0f) ? 0xFFu : 0u;  if (v3 >= 1.0f) v3 = 0.f;
        *reinterpret_cast<uchar4*>(g_spikes + (size_t)t * ELEMS_T + i) = s;
    }
}

// ---------------------------------------------------------------------------
// helpers
// ---------------------------------------------------------------------------
__device__ __forceinline__ uint32_t packh2(float lo, float hi) {
    uint32_t r;
    asm("cvt.rn.f16x2.f32 %0, %1, %2;" : "=r"(r) : "f"(hi), "f"(lo));
    return r;
}
__device__ __forceinline__ void mma_f16(float& c0, float& c1, float& c2, float& c3,
                                        uint32_t a0, uint32_t a1, uint32_t a2, uint32_t a3,
                                        uint32_t b0, uint32_t b1)
{
    asm volatile(
        "mma.sync.aligned.m16n8k16.row.col.f32.f16.f16.f32 "
        "{%0,%1,%2,%3}, {%4,%5,%6,%7}, {%8,%9}, {%0,%1,%2,%3};"
        : "+f"(c0), "+f"(c1), "+f"(c2), "+f"(c3)
        : "r"(a0), "r"(a1), "r"(a2), "r"(a3), "r"(b0), "r"(b1));
}
// spike byte (0xFF/0x00) -> 1.0f/0.0f : sign-mode PRMT + AND
__device__ __forceinline__ float spike_f(uint32_t word, int byte_idx) {
    uint32_t m = __byte_perm(word, 0u, 0x8888u + 0x1111u * (uint32_t)byte_idx);
    return __int_as_float((int)(m & 0x3f800000u));
}

// ---------------------------------------------------------------------------
// Kernel 2: persistent fused dw3x3 (CUDA cores) + pw1x1+BN (mma.sync fp16)
//
// B tile in SMEM: fp16 pairs. word Bp[kw][n'] = (dw[ch=kw][n], dw[ch=kw+64][n])
//   n' = (n&7)*16 + (n>>3);  k-permutation: k'=2kw -> ch kw, k'=2kw+1 -> ch kw+64
// SMEM (bytes):
//   0     : s_bias [128] f32
//   512   : s_dww  [1152] f32
//   5120  : s_sp   spike tile 128ch * 304B (6 rows * 48B pitch)
//   44032 : s_B    64(kw) x 132-word stride (fp16x2 words)
// ---------------------------------------------------------------------------
#define OFF_BIAS  0
#define OFF_DWW   512
#define OFF_SP    5120
#define SP_CH     304
#define OFF_B     44032
#define BSTRIDE   132
#define SMEM_TOTAL (OFF_B + 64*BSTRIDE*4)   // 77824

__device__ __forceinline__ void load_spikes(unsigned char* s_sp, int t, int tid)
{
    int img  = t >> 3;
    int row0 = (t & 7) * 4;
    const unsigned char* gsp = g_spikes + (size_t)img * SP_IMG;
    int cc = tid & 127, rb = tid >> 7;
#pragma unroll
    for (int j = 0; j < 3; j++) {
        int rl = rb + j * 2;                 // 0..5
        int gr = row0 - 1 + rl;
        uint32_t* dst = reinterpret_cast<uint32_t*>(s_sp + cc * SP_CH + rl * 48 + 4);
        if ((unsigned)gr < 32u) {
            const uint4* src = reinterpret_cast<const uint4*>(gsp + cc * 1024 + gr * 32);
            uint4 a = src[0], b = src[1];
            dst[0] = a.x; dst[1] = a.y; dst[2] = a.z; dst[3] = a.w;
            dst[4] = b.x; dst[5] = b.y; dst[6] = b.z; dst[7] = b.w;
        } else {
#pragma unroll
            for (int k = 0; k < 8; k++) dst[k] = 0u;
        }
    }
}

__global__ __launch_bounds__(NTHREADS, 1) void fused_mma_kernel(
    const float* __restrict__ dw_w,  const float* __restrict__ dw_b,
    const float* __restrict__ pw_w,  const float* __restrict__ pw_b,
    const float* __restrict__ gamma, const float* __restrict__ beta,
    const float* __restrict__ rmean, const float* __restrict__ rvar,
    float* __restrict__ out)
{
    extern __shared__ unsigned char smem[];
    float*    s_bias = reinterpret_cast<float*>(smem + OFF_BIAS);
    float*    s_dww  = reinterpret_cast<float*>(smem + OFF_DWW);
    unsigned char* s_sp = smem + OFF_SP;
    uint32_t* s_B    = reinterpret_cast<uint32_t*>(smem + OFF_B);

    const int tid = threadIdx.x;
    const int wid = tid >> 5;
    const int lid = tid & 31;
    const int g   = lid >> 2;      // 0..7
    const int t4  = lid & 3;       // 0..3
    const int mg  = wid & 3;       // m-group
    const int ng  = wid >> 2;      // n-group
    const int ob  = mg * 32;       // warp out-channel base
    const int nb  = ng * 64;       // warp pixel base

    // ---- one-time setup ----
    {
        uint4 z = make_uint4(0u, 0u, 0u, 0u);
        uint4* p4 = reinterpret_cast<uint4*>(s_sp);
        for (int i = tid; i < (128 * SP_CH) / 16; i += NTHREADS) p4[i] = z;
    }
    for (int i = tid; i < 1152; i += NTHREADS) s_dww[i] = dw_w[i];
    if (tid < 128) {   // fold dw bias + BN shift + pw bias per-o
        int o = tid;
        float sc = gamma[o] * rsqrtf(rvar[o] + 1e-5f);
        float s = 0.f;
        for (int c = 0; c < 128; c++) s += pw_w[o * 128 + c] * dw_b[c];
        s_bias[o] = beta[o] + sc * (pw_b[o] - rmean[o] + s);
    }

    // ---- A fragments (BN-scaled pw weights, fp16, k-permuted) : persistent ----
    uint32_t af[8][2][4];
#pragma unroll
    for (int mt = 0; mt < 2; mt++) {
        int o0 = ob + mt * 16 + g;
        int o1 = o0 + 8;
        float s0 = gamma[o0] * rsqrtf(rvar[o0] + 1e-5f);
        float s1 = gamma[o1] * rsqrtf(rvar[o1] + 1e-5f);
        const float* w0 = pw_w + o0 * 128;
        const float* w1 = pw_w + o1 * 128;
#pragma unroll
        for (int ks = 0; ks < 8; ks++) {
            int cl = ks * 8 + t4;
            af[ks][mt][0] = packh2(w0[cl]     * s0, w0[cl + 64] * s0);
            af[ks][mt][1] = packh2(w1[cl]     * s1, w1[cl + 64] * s1);
            af[ks][mt][2] = packh2(w0[cl + 4] * s0, w0[cl + 68] * s0);
            af[ks][mt][3] = packh2(w1[cl + 4] * s1, w1[cl + 68] * s1);
        }
    }
    __syncthreads();

    // ---- dw-stage thread mapping: (cp, row) ; channels cp and cp+64 ----
    const int cp  = tid & 63;
    const int row = tid >> 6;            // 0..3
    float w0r[9], w1r[9];
#pragma unroll
    for (int i = 0; i < 9; i++) { w0r[i] = s_dww[cp * 9 + i]; w1r[i] = s_dww[(cp + 64) * 9 + i]; }
    const unsigned char* sp0 = s_sp + cp * SP_CH + row * 48;
    const unsigned char* sp1 = s_sp + (cp + 64) * SP_CH + row * 48;
    uint32_t* bst = s_B + cp * BSTRIDE + row * 4;

    const uint32_t* bld = s_B + t4 * BSTRIDE + g * 16 + ng * 8;

    const float bias00 = s_bias[ob + g];
    const float bias01 = s_bias[ob + g + 8];
    const float bias10 = s_bias[ob + 16 + g];
    const float bias11 = s_bias[ob + 24 + g];

    int t = blockIdx.x;
    load_spikes(s_sp, t, tid);
    __syncthreads();

    for (; t < NTILES; t += GRID) {
        // ================= depthwise 3x3 (2 channels x 32 px) =================
        float out0[32], out1[32];
#pragma unroll
        for (int i = 0; i < 32; i++) { out0[i] = 0.f; out1[i] = 0.f; }
#pragma unroll
        for (int half = 0; half < 2; half++) {
            const unsigned char* sp = half ? sp1 : sp0;
            const float* w = half ? w1r : w0r;
            float* o = half ? out1 : out0;
#pragma unroll
            for (int rr = 0; rr < 3; rr++) {
                const uint4* r4 = reinterpret_cast<const uint4*>(sp + rr * 48);
                uint4 ua = r4[0], ub = r4[1], uc = r4[2];
                uint32_t uu[12] = {ua.x, ua.y, ua.z, ua.w, ub.x, ub.y, ub.z, ub.w,
                                   uc.x, uc.y, uc.z, uc.w};
                float f[34];
#pragma unroll
                for (int j = 0; j < 34; j++) {
                    int b = j + 3;
                    f[j] = spike_f(uu[b >> 2], b & 3);
                }
                const float wa = w[rr * 3], wb = w[rr * 3 + 1], wc = w[rr * 3 + 2];
#pragma unroll
                for (int col = 0; col < 32; col++)
                    o[col] += wa * f[col] + wb * f[col + 1] + wc * f[col + 2];
            }
        }
        // store B: fp16 pairs, permuted layout, conflict-free STS.128
#pragma unroll
        for (int j = 0; j < 8; j++) {
            uint4 v;
            v.x = packh2(out0[j],      out1[j]);
            v.y = packh2(out0[j + 8],  out1[j + 8]);
            v.z = packh2(out0[j + 16], out1[j + 16]);
            v.w = packh2(out0[j + 24], out1[j + 24]);
            *reinterpret_cast<uint4*>(bst + j * 16) = v;
        }
        __syncthreads();

        // ================= GEMM: 32o x 64px x 128c per warp (fp16 HMMA) =========
        float acc[2][8][4];
#pragma unroll
        for (int mt = 0; mt < 2; mt++)
#pragma unroll
            for (int nt = 0; nt < 8; nt++)
#pragma unroll
                for (int r = 0; r < 4; r++) acc[mt][nt][r] = 0.f;

#pragma unroll
        for (int s = 0; s < 8; s++) {
            const uint32_t* bp = bld + (8 * s) * BSTRIDE;
            uint4 u0 = *reinterpret_cast<const uint4*>(bp);
            uint4 u1 = *reinterpret_cast<const uint4*>(bp + 4);
            uint4 u2 = *reinterpret_cast<const uint4*>(bp + 4 * BSTRIDE);
            uint4 u3 = *reinterpret_cast<const uint4*>(bp + 4 * BSTRIDE + 4);
            uint32_t b0[8] = {u0.x, u0.y, u0.z, u0.w, u1.x, u1.y, u1.z, u1.w};
            uint32_t b1[8] = {u2.x, u2.y, u2.z, u2.w, u3.x, u3.y, u3.z, u3.w};
#pragma unroll
            for (int nt = 0; nt < 8; nt++) {
                mma_f16(acc[0][nt][0], acc[0][nt][1], acc[0][nt][2], acc[0][nt][3],
                        af[s][0][0], af[s][0][1], af[s][0][2], af[s][0][3],
                        b0[nt], b1[nt]);
                mma_f16(acc[1][nt][0], acc[1][nt][1], acc[1][nt][2], acc[1][nt][3],
                        af[s][1][0], af[s][1][1], af[s][1][2], af[s][1][3],
                        b0[nt], b1[nt]);
            }
        }

        // ---- prefetch next spike tile ----
        int tn = t + GRID;
        if (tn < NTILES) load_spikes(s_sp, tn, tid);

        // ================= epilogue: bias + store =================
        {
            const int img = t >> 3, ptile = t & 7;
            float* obase = out + (size_t)img * (COUT * HW) + ptile * 128 + nb + 2 * t4;
#pragma unroll
            for (int mt = 0; mt < 2; mt++) {
                const float blo = (mt == 0) ? bias00 : bias10;
                const float bhi = (mt == 0) ? bias01 : bias11;
                float* r0 = obase + (size_t)(ob + mt * 16 + g) * HW;
#pragma unroll
                for (int nt = 0; nt < 8; nt++) {
                    float2 v0 = make_float2(acc[mt][nt][0] + blo, acc[mt][nt][1] + blo);
                    float2 v1 = make_float2(acc[mt][nt][2] + bhi, acc[mt][nt][3] + bhi);
                    *reinterpret_cast<float2*>(r0 + nt * 8)          = v0;
                    *reinterpret_cast<float2*>(r0 + 8 * HW + nt * 8) = v1;
                }
            }
        }
        __syncthreads();
    }
}

// ---------------------------------------------------------------------------
// Launcher
// ---------------------------------------------------------------------------
extern "C" void kernel_launch(void* const* d_in, const int* in_sizes, int n_in,
                              void* d_out, int out_size)
{
    const float* x     = (const float*)d_in[0];
    const float* dw_w  = (const float*)d_in[1];
    const float* dw_b  = (const float*)d_in[2];
    const float* pw_w  = (const float*)d_in[3];
    const float* pw_b  = (const float*)d_in[4];
    const float* gamma = (const float*)d_in[5];
    const float* beta  = (const float*)d_in[6];
    const float* rmean = (const float*)d_in[7];
    const float* rvar  = (const float*)d_in[8];
    float* out = (float*)d_out;

    lif_kernel<<<ELEMS_T / (256 * 4), 256>>>(x);

    cudaFuncSetAttribute(fused_mma_kernel,
                         cudaFuncAttributeMaxDynamicSharedMemorySize, SMEM_TOTAL);
    fused_mma_kernel<<<GRID, NTHREADS, SMEM_TOTAL>>>(dw_w, dw_b, pw_w, pw_b,
                                                     gamma, beta, rmean, rvar, out);
}

// round 5
// speedup vs baseline: 2.8565x; 1.0182x over previous
#include <cuda_runtime.h>
#include <cstdint>

#define T_STEPS 16
#define NB      32
#define HH      32
#define WW      32
#define COUT    128
#define HW      (HH*WW)
#define ELEMS_T (NB*128*HH*WW)
#define IMGS    (T_STEPS*NB)
#define SP_IMG  (128*HW)
#define NTILES  (IMGS*8)
#define GRID    304
#define NTHREADS 256

__device__ unsigned char g_spikes[(size_t)T_STEPS * ELEMS_T];

// ---------------------------------------------------------------------------
// Kernel 1: LIF scan (spikes stored as 0xFF/0x00 for sign-PRMT conversion)
// ---------------------------------------------------------------------------
__global__ __launch_bounds__(256) void lif_kernel(const float* __restrict__ x)
{
    int i = (blockIdx.x * 256 + threadIdx.x) * 4;
    if (i >= ELEMS_T) return;
    float v0 = 0.f, v1 = 0.f, v2 = 0.f, v3 = 0.f;
#pragma unroll
    for (int t = 0; t < T_STEPS; t++) {
        float4 xv = *reinterpret_cast<const float4*>(x + (size_t)t * ELEMS_T + i);
        v0 = v0 + (xv.x - v0) * 0.5f;
        v1 = v1 + (xv.y - v1) * 0.5f;
        v2 = v2 + (xv.z - v2) * 0.5f;
        v3 = v3 + (xv.w - v3) * 0.5f;
        uchar4 s;
        s.x = (v0 >= 1.0f) ? 0xFFu : 0u;  if (v0 >= 1.0f) v0 = 0.f;
        s.y = (v1 >= 1.0f) ? 0xFFu : 0u;  if (v1 >= 1.0f) v1 = 0.f;
        s.z = (v2 >= 1.0f) ? 0xFFu : 0u;  if (v2 >= 1.0f) v2 = 0.f;
        s.w = (v3 >= 1.0f) ? 0xFFu : 0u;  if (v3 >= 1.0f) v3 = 0.f;
        *reinterpret_cast<uchar4*>(g_spikes + (size_t)t * ELEMS_T + i) = s;
    }
}

// ---------------------------------------------------------------------------
// helpers
// ---------------------------------------------------------------------------
__device__ __forceinline__ uint32_t packh2(float lo, float hi) {
    uint32_t r;
    asm("cvt.rn.f16x2.f32 %0, %1, %2;" : "=r"(r) : "f"(hi), "f"(lo));
    return r;
}
__device__ __forceinline__ void mma_f16(float& c0, float& c1, float& c2, float& c3,
                                        uint32_t a0, uint32_t a1, uint32_t a2, uint32_t a3,
                                        uint32_t b0, uint32_t b1)
{
    asm volatile(
        "mma.sync.aligned.m16n8k16.row.col.f32.f16.f16.f32 "
        "{%0,%1,%2,%3}, {%4,%5,%6,%7}, {%8,%9}, {%0,%1,%2,%3};"
        : "+f"(c0), "+f"(c1), "+f"(c2), "+f"(c3)
        : "r"(a0), "r"(a1), "r"(a2), "r"(a3), "r"(b0), "r"(b1));
}
// spike byte (0xFF/0x00) -> 1.0f/0.0f : sign-mode PRMT + AND
__device__ __forceinline__ float spike_f(uint32_t word, int byte_idx) {
    uint32_t m = __byte_perm(word, 0u, 0x8888u + 0x1111u * (uint32_t)byte_idx);
    return __int_as_float((int)(m & 0x3f800000u));
}

// ---------------------------------------------------------------------------
// Kernel 2: persistent fused dw3x3 + pw1x1+BN (mma.sync fp16), 2 CTAs/SM
//
// SMEM (bytes):
//   0     : s_bias [128] f32
//   512   : s_dww  [1152] f32
//   5120  : s_sp   spike tile 128ch * 304B
//   44032 : s_B    64(kw) x 132-word stride (fp16x2 words)   33792 B
//   77824 : s_A    64 segs x 32 lanes x uint4 (A fragments)  32768 B
// total  : 110592 B  -> 2 CTAs/SM
// ---------------------------------------------------------------------------
#define OFF_BIAS  0
#define OFF_DWW   512
#define OFF_SP    5120
#define SP_CH     304
#define OFF_B     44032
#define BSTRIDE   132
#define OFF_A     77824
#define SMEM_TOTAL (OFF_A + 32768)   // 110592

__device__ __forceinline__ void load_spikes(unsigned char* s_sp, int t, int tid)
{
    int img  = t >> 3;
    int row0 = (t & 7) * 4;
    const unsigned char* gsp = g_spikes + (size_t)img * SP_IMG;
    int cc = tid & 127, rb = tid >> 7;
#pragma unroll
    for (int j = 0; j < 3; j++) {
        int rl = rb + j * 2;                 // 0..5
        int gr = row0 - 1 + rl;
        uint32_t* dst = reinterpret_cast<uint32_t*>(s_sp + cc * SP_CH + rl * 48 + 4);
        if ((unsigned)gr < 32u) {
            const uint4* src = reinterpret_cast<const uint4*>(gsp + cc * 1024 + gr * 32);
            uint4 a = src[0], b = src[1];
            dst[0] = a.x; dst[1] = a.y; dst[2] = a.z; dst[3] = a.w;
            dst[4] = b.x; dst[5] = b.y; dst[6] = b.z; dst[7] = b.w;
        } else {
#pragma unroll
            for (int k = 0; k < 8; k++) dst[k] = 0u;
        }
    }
}

__global__ __launch_bounds__(NTHREADS, 2) void fused_mma_kernel(
    const float* __restrict__ dw_w,  const float* __restrict__ dw_b,
    const float* __restrict__ pw_w,  const float* __restrict__ pw_b,
    const float* __restrict__ gamma, const float* __restrict__ beta,
    const float* __restrict__ rmean, const float* __restrict__ rvar,
    float* __restrict__ out)
{
    extern __shared__ unsigned char smem[];
    float*    s_bias = reinterpret_cast<float*>(smem + OFF_BIAS);
    float*    s_dww  = reinterpret_cast<float*>(smem + OFF_DWW);
    unsigned char* s_sp = smem + OFF_SP;
    uint32_t* s_B    = reinterpret_cast<uint32_t*>(smem + OFF_B);
    uint32_t* s_A    = reinterpret_cast<uint32_t*>(smem + OFF_A);

    const int tid = threadIdx.x;
    const int wid = tid >> 5;
    const int lid = tid & 31;
    const int g   = lid >> 2;      // 0..7
    const int t4  = lid & 3;       // 0..3
    const int mg  = wid & 3;       // m-group
    const int ng  = wid >> 2;      // n-group
    const int ob  = mg * 32;       // warp out-channel base
    const int nb  = ng * 64;       // warp pixel base

    // ---- one-time setup ----
    {
        uint4 z = make_uint4(0u, 0u, 0u, 0u);
        uint4* p4 = reinterpret_cast<uint4*>(s_sp);
        for (int i = tid; i < (128 * SP_CH) / 16; i += NTHREADS) p4[i] = z;
    }
    for (int i = tid; i < 1152; i += NTHREADS) s_dww[i] = dw_w[i];
    if (tid < 128) {   // fold dw bias + BN shift + pw bias per-o
        int o = tid;
        float sc = gamma[o] * rsqrtf(rvar[o] + 1e-5f);
        float s = 0.f;
        for (int c = 0; c < 128; c++) s += pw_w[o * 128 + c] * dw_b[c];
        s_bias[o] = beta[o] + sc * (pw_b[o] - rmean[o] + s);
    }
    // ---- A fragments into SMEM (BN-scaled pw weights, fp16, k-permuted) ----
    // seg = mg*16 + mt*8 + ks ; entry (seg, lane) is the uint4 fragment for
    // warp-group mg, m-tile mt, k-step ks, lane (g,t4).
    for (int i = tid; i < 2048; i += NTHREADS) {
        int seg  = i >> 5, lane = i & 31;
        int smg  = seg >> 4, smt = (seg >> 3) & 1, sks = seg & 7;
        int sg   = lane >> 2, st4 = lane & 3;
        int o0   = smg * 32 + smt * 16 + sg;
        int o1   = o0 + 8;
        float s0 = gamma[o0] * rsqrtf(rvar[o0] + 1e-5f);
        float s1 = gamma[o1] * rsqrtf(rvar[o1] + 1e-5f);
        const float* w0 = pw_w + o0 * 128;
        const float* w1 = pw_w + o1 * 128;
        int cl = sks * 8 + st4;
        uint4 v;
        v.x = packh2(w0[cl]     * s0, w0[cl + 64] * s0);
        v.y = packh2(w1[cl]     * s1, w1[cl + 64] * s1);
        v.z = packh2(w0[cl + 4] * s0, w0[cl + 68] * s0);
        v.w = packh2(w1[cl + 4] * s1, w1[cl + 68] * s1);
        *reinterpret_cast<uint4*>(s_A + (size_t)i * 4) = v;
    }
    __syncthreads();

    // ---- dw-stage thread mapping: (cp, row); channels cp and cp+64 ----
    const int cp  = tid & 63;
    const int row = tid >> 6;            // 0..3
    float w0r[9], w1r[9];
#pragma unroll
    for (int i = 0; i < 9; i++) { w0r[i] = s_dww[cp * 9 + i]; w1r[i] = s_dww[(cp + 64) * 9 + i]; }
    const unsigned char* sp0 = s_sp + cp * SP_CH + row * 48;
    const unsigned char* sp1 = s_sp + (cp + 64) * SP_CH + row * 48;
    uint32_t* bst = s_B + cp * BSTRIDE + row * 4;

    const uint32_t* bld = s_B + t4 * BSTRIDE + g * 16 + ng * 8;
    const uint32_t* ald = s_A + (size_t)(mg * 16) * 128 + lid * 4;

    int t = blockIdx.x;
    load_spikes(s_sp, t, tid);
    __syncthreads();

    for (; t < NTILES; t += GRID) {
        // ================= depthwise 3x3 (2 channels x 32 px) =================
        float out0[32], out1[32];
#pragma unroll
        for (int i = 0; i < 32; i++) { out0[i] = 0.f; out1[i] = 0.f; }
#pragma unroll
        for (int half = 0; half < 2; half++) {
            const unsigned char* sp = half ? sp1 : sp0;
            const float* w = half ? w1r : w0r;
            float* o = half ? out1 : out0;
#pragma unroll
            for (int rr = 0; rr < 3; rr++) {
                const uint4* r4 = reinterpret_cast<const uint4*>(sp + rr * 48);
                uint4 ua = r4[0], ub = r4[1], uc = r4[2];
                uint32_t uu[12] = {ua.x, ua.y, ua.z, ua.w, ub.x, ub.y, ub.z, ub.w,
                                   uc.x, uc.y, uc.z, uc.w};
                float f[34];
#pragma unroll
                for (int j = 0; j < 34; j++) {
                    int b = j + 3;
                    f[j] = spike_f(uu[b >> 2], b & 3);
                }
                const float wa = w[rr * 3], wb = w[rr * 3 + 1], wc = w[rr * 3 + 2];
#pragma unroll
                for (int col = 0; col < 32; col++)
                    o[col] += wa * f[col] + wb * f[col + 1] + wc * f[col + 2];
            }
        }
        // store B: fp16 pairs, permuted layout, conflict-free STS.128
#pragma unroll
        for (int j = 0; j < 8; j++) {
            uint4 v;
            v.x = packh2(out0[j],      out1[j]);
            v.y = packh2(out0[j + 8],  out1[j + 8]);
            v.z = packh2(out0[j + 16], out1[j + 16]);
            v.w = packh2(out0[j + 24], out1[j + 24]);
            *reinterpret_cast<uint4*>(bst + j * 16) = v;
        }
        __syncthreads();

        // ================= GEMM: 32o x 64px x 128c per warp (fp16 HMMA) =========
        float acc[2][8][4];
#pragma unroll
        for (int mt = 0; mt < 2; mt++)
#pragma unroll
            for (int nt = 0; nt < 8; nt++)
#pragma unroll
                for (int r = 0; r < 4; r++) acc[mt][nt][r] = 0.f;

#pragma unroll
        for (int s = 0; s < 8; s++) {
            const uint32_t* bp = bld + (8 * s) * BSTRIDE;
            uint4 u0 = *reinterpret_cast<const uint4*>(bp);
            uint4 u1 = *reinterpret_cast<const uint4*>(bp + 4);
            uint4 u2 = *reinterpret_cast<const uint4*>(bp + 4 * BSTRIDE);
            uint4 u3 = *reinterpret_cast<const uint4*>(bp + 4 * BSTRIDE + 4);
            uint4 a0 = *reinterpret_cast<const uint4*>(ald + (size_t)s * 128);
            uint4 a1 = *reinterpret_cast<const uint4*>(ald + (size_t)(s + 8) * 128);
            uint32_t b0[8] = {u0.x, u0.y, u0.z, u0.w, u1.x, u1.y, u1.z, u1.w};
            uint32_t b1[8] = {u2.x, u2.y, u2.z, u2.w, u3.x, u3.y, u3.z, u3.w};
#pragma unroll
            for (int nt = 0; nt < 8; nt++) {
                mma_f16(acc[0][nt][0], acc[0][nt][1], acc[0][nt][2], acc[0][nt][3],
                        a0.x, a0.y, a0.z, a0.w, b0[nt], b1[nt]);
                mma_f16(acc[1][nt][0], acc[1][nt][1], acc[1][nt][2], acc[1][nt][3],
                        a1.x, a1.y, a1.z, a1.w, b0[nt], b1[nt]);
            }
        }

        // ---- prefetch next spike tile ----
        int tn = t + GRID;
        if (tn < NTILES) load_spikes(s_sp, tn, tid);

        // ================= epilogue: bias + store =================
        {
            const int img = t >> 3, ptile = t & 7;
            float* obase = out + (size_t)img * (COUT * HW) + ptile * 128 + nb + 2 * t4;
#pragma unroll
            for (int mt = 0; mt < 2; mt++) {
                const float blo = s_bias[ob + mt * 16 + g];
                const float bhi = s_bias[ob + mt * 16 + g + 8];
                float* r0 = obase + (size_t)(ob + mt * 16 + g) * HW;
#pragma unroll
                for (int nt = 0; nt < 8; nt++) {
                    float2 v0 = make_float2(acc[mt][nt][0] + blo, acc[mt][nt][1] + blo);
                    float2 v1 = make_float2(acc[mt][nt][2] + bhi, acc[mt][nt][3] + bhi);
                    *reinterpret_cast<float2*>(r0 + nt * 8)          = v0;
                    *reinterpret_cast<float2*>(r0 + 8 * HW + nt * 8) = v1;
                }
            }
        }
        __syncthreads();
    }
}

// ---------------------------------------------------------------------------
// Launcher
// ---------------------------------------------------------------------------
extern "C" void kernel_launch(void* const* d_in, const int* in_sizes, int n_in,
                              void* d_out, int out_size)
{
    const float* x     = (const float*)d_in[0];
    const float* dw_w  = (const float*)d_in[1];
    const float* dw_b  = (const float*)d_in[2];
    const float* pw_w  = (const float*)d_in[3];
    const float* pw_b  = (const float*)d_in[4];
    const float* gamma = (const float*)d_in[5];
    const float* beta  = (const float*)d_in[6];
    const float* rmean = (const float*)d_in[7];
    const float* rvar  = (const float*)d_in[8];
    float* out = (float*)d_out;

    lif_kernel<<<ELEMS_T / (256 * 4), 256>>>(x);

    cudaFuncSetAttribute(fused_mma_kernel,
                         cudaFuncAttributeMaxDynamicSharedMemorySize, SMEM_TOTAL);
    fused_mma_kernel<<<GRID, NTHREADS, SMEM_TOTAL>>>(dw_w, dw_b, pw_w, pw_b,
                                                     gamma, beta, rmean, rvar, out);
}

// round 6
// speedup vs baseline: 3.3166x; 1.1611x over previous
#include <cuda_runtime.h>
#include <cstdint>

#define T_STEPS 16
#define NB      32
#define HH      32
#define WW      32
#define COUT    128
#define HW      (HH*WW)
#define ELEMS_T (NB*128*HH*WW)
#define IMGS    (T_STEPS*NB)
#define NTILES  (IMGS*8)
#define GRID    152
#define NTHREADS 256

// Bit-packed spikes: word (img, h, c) = 32 px of row h, channel c.
__device__ uint32_t g_spk[(size_t)IMGS * 32 * 128];

// ---------------------------------------------------------------------------
// Kernel 1: LIF scan -> bit-packed spikes
// ---------------------------------------------------------------------------
__global__ __launch_bounds__(256) void lif_kernel(const float* __restrict__ x)
{
    const int i = (blockIdx.x * 256 + threadIdx.x) * 4;   // px index, w fastest
    if (i >= ELEMS_T) return;
    const int lane = threadIdx.x & 31;
    const int w0   = i & 31;                              // = 4*(lane&7)
    // word address components (constant across the 8-lane group)
    const size_t waddr = ((size_t)(i >> 17)) * 4096        // n
                       + (size_t)((i >> 5) & 31) * 128     // h
                       + (size_t)((i >> 10) & 127);        // c
    float v0 = 0.f, v1 = 0.f, v2 = 0.f, v3 = 0.f;
#pragma unroll
    for (int t = 0; t < T_STEPS; t++) {
        float4 xv = *reinterpret_cast<const float4*>(x + (size_t)t * ELEMS_T + i);
        v0 = v0 + (xv.x - v0) * 0.5f;
        v1 = v1 + (xv.y - v1) * 0.5f;
        v2 = v2 + (xv.z - v2) * 0.5f;
        v3 = v3 + (xv.w - v3) * 0.5f;
        uint32_t nib = (v0 >= 1.0f ? 1u : 0u) | (v1 >= 1.0f ? 2u : 0u)
                     | (v2 >= 1.0f ? 4u : 0u) | (v3 >= 1.0f ? 8u : 0u);
        if (v0 >= 1.0f) v0 = 0.f;
        if (v1 >= 1.0f) v1 = 0.f;
        if (v2 >= 1.0f) v2 = 0.f;
        if (v3 >= 1.0f) v3 = 0.f;
        uint32_t m = nib << w0;
        m |= __shfl_xor_sync(0xFFFFFFFFu, m, 1);
        m |= __shfl_xor_sync(0xFFFFFFFFu, m, 2);
        m |= __shfl_xor_sync(0xFFFFFFFFu, m, 4);
        if ((lane & 7) == 0)
            g_spk[(size_t)t * (NB * 4096) + waddr] = m;
    }
}

// ---------------------------------------------------------------------------
// helpers
// ---------------------------------------------------------------------------
__device__ __forceinline__ uint32_t packh2(float lo, float hi) {
    uint32_t r;
    asm("cvt.rn.f16x2.f32 %0, %1, %2;" : "=r"(r) : "f"(hi), "f"(lo));
    return r;
}
__device__ __forceinline__ void mma_f16(float& c0, float& c1, float& c2, float& c3,
                                        uint32_t a0, uint32_t a1, uint32_t a2, uint32_t a3,
                                        uint32_t b0, uint32_t b1)
{
    asm volatile(
        "mma.sync.aligned.m16n8k16.row.col.f32.f16.f16.f32 "
        "{%0,%1,%2,%3}, {%4,%5,%6,%7}, {%8,%9}, {%0,%1,%2,%3};"
        : "+f"(c0), "+f"(c1), "+f"(c2), "+f"(c3)
        : "r"(a0), "r"(a1), "r"(a2), "r"(a3), "r"(b0), "r"(b1));
}

// ---------------------------------------------------------------------------
// SMEM layout (bytes)
// ---------------------------------------------------------------------------
#define OFF_BIAS  0
#define OFF_DWW   512
#define OFF_SPK0  5120                      // 6 rows x 128 ch words = 3072 B
#define OFF_SPK1  8192
#define OFF_B0    11264                     // 64 kw x 132-word stride = 33792 B
#define OFF_B1    45056
#define BSTRIDE   132
#define SMEM_TOTAL 78848

// load 6 spike rows (r0-1 .. r0+4) x 128 channels, coalesced LDG.32
__device__ __forceinline__ void load_spk(uint32_t* dst, int t, int tid)
{
    const int img = t >> 3, r0 = (t & 7) * 4;
    const uint32_t* g = g_spk + (size_t)img * 4096;
    const int c = tid & 127, half = tid >> 7;
#pragma unroll
    for (int j = 0; j < 3; j++) {
        int rl = half * 3 + j;
        int gr = r0 - 1 + rl;
        uint32_t v = 0u;
        if ((unsigned)gr < 32u) v = g[gr * 128 + c];
        dst[rl * 128 + c] = v;
    }
}

// depthwise 3x3 for one channel-half: channel c, output row 'row' (0..3),
// reading smem spike rows row..row+2, accumulating 32 px into o[].
__device__ __forceinline__ void dw_half(const uint32_t* spk, int row, int c,
                                        const float (&w)[9], float (&o)[32])
{
#pragma unroll
    for (int rr = 0; rr < 3; rr++) {
        uint32_t wrd = spk[(row + rr) * 128 + c];
        float f[34];
        f[0] = 0.f; f[33] = 0.f;
#pragma unroll
        for (int j = 1; j <= 32; j++)
            f[j] = __int_as_float(((wrd >> (j - 1)) & 1u) * 0x3f800000u);
        const float wa = w[rr * 3], wb = w[rr * 3 + 1], wc = w[rr * 3 + 2];
#pragma unroll
        for (int col = 0; col < 32; col++)
            o[col] += wa * f[col] + wb * f[col + 1] + wc * f[col + 2];
    }
}

// full dw stage for one tile: thread (cp,row) does channels cp & cp+64
__device__ __forceinline__ void dw_tile(const uint32_t* spk, uint32_t* bst,
                                        const float (&w0r)[9], const float (&w1r)[9],
                                        int cp, int row)
{
    float o0[32], o1[32];
#pragma unroll
    for (int i = 0; i < 32; i++) { o0[i] = 0.f; o1[i] = 0.f; }
    dw_half(spk, row, cp,      w0r, o0);
    dw_half(spk, row, cp + 64, w1r, o1);
#pragma unroll
    for (int j = 0; j < 8; j++) {
        uint4 v;
        v.x = packh2(o0[j],      o1[j]);
        v.y = packh2(o0[j + 8],  o1[j + 8]);
        v.z = packh2(o0[j + 16], o1[j + 16]);
        v.w = packh2(o0[j + 24], o1[j + 24]);
        *reinterpret_cast<uint4*>(bst + j * 16) = v;
    }
}

// ---------------------------------------------------------------------------
// Kernel 2: pipelined fused dw3x3 + pw1x1+BN (mma.sync fp16)
// ---------------------------------------------------------------------------
__global__ __launch_bounds__(NTHREADS) void fused_mma_kernel(
    const float* __restrict__ dw_w,  const float* __restrict__ dw_b,
    const float* __restrict__ pw_w,  const float* __restrict__ pw_b,
    const float* __restrict__ gamma, const float* __restrict__ beta,
    const float* __restrict__ rmean, const float* __restrict__ rvar,
    float* __restrict__ out)
{
    extern __shared__ unsigned char smem[];
    float*    s_bias = reinterpret_cast<float*>(smem + OFF_BIAS);
    float*    s_dww  = reinterpret_cast<float*>(smem + OFF_DWW);
    uint32_t* spk0   = reinterpret_cast<uint32_t*>(smem + OFF_SPK0);
    uint32_t* spk1   = reinterpret_cast<uint32_t*>(smem + OFF_SPK1);
    uint32_t* sB0    = reinterpret_cast<uint32_t*>(smem + OFF_B0);
    uint32_t* sB1    = reinterpret_cast<uint32_t*>(smem + OFF_B1);

    const int tid = threadIdx.x;
    const int wid = tid >> 5;
    const int lid = tid & 31;
    const int g   = lid >> 2;
    const int t4  = lid & 3;
    const int mg  = wid & 3;
    const int ng  = wid >> 2;
    const int ob  = mg * 32;
    const int nb  = ng * 64;

    // ---- one-time setup ----
    for (int i = tid; i < 1152; i += NTHREADS) s_dww[i] = dw_w[i];
    if (tid < 128) {
        int o = tid;
        float sc = gamma[o] * rsqrtf(rvar[o] + 1e-5f);
        float s = 0.f;
        for (int c = 0; c < 128; c++) s += pw_w[o * 128 + c] * dw_b[c];
        s_bias[o] = beta[o] + sc * (pw_b[o] - rmean[o] + s);
    }

    // ---- A fragments in registers (BN-scaled pw weights, fp16, k-permuted) ----
    uint32_t af[8][2][4];
#pragma unroll
    for (int mt = 0; mt < 2; mt++) {
        int o0 = ob + mt * 16 + g;
        int o1 = o0 + 8;
        float s0 = gamma[o0] * rsqrtf(rvar[o0] + 1e-5f);
        float s1 = gamma[o1] * rsqrtf(rvar[o1] + 1e-5f);
        const float* w0 = pw_w + o0 * 128;
        const float* w1 = pw_w + o1 * 128;
#pragma unroll
        for (int ks = 0; ks < 8; ks++) {
            int cl = ks * 8 + t4;
            af[ks][mt][0] = packh2(w0[cl]     * s0, w0[cl + 64] * s0);
            af[ks][mt][1] = packh2(w1[cl]     * s1, w1[cl + 64] * s1);
            af[ks][mt][2] = packh2(w0[cl + 4] * s0, w0[cl + 68] * s0);
            af[ks][mt][3] = packh2(w1[cl + 4] * s1, w1[cl + 68] * s1);
        }
    }
    __syncthreads();

    // ---- per-thread constants ----
    const int cp  = tid & 63;
    const int row = tid >> 6;
    float w0r[9], w1r[9];
#pragma unroll
    for (int i = 0; i < 9; i++) { w0r[i] = s_dww[cp * 9 + i]; w1r[i] = s_dww[(cp + 64) * 9 + i]; }
    uint32_t* bst0 = sB0 + cp * BSTRIDE + row * 4;
    uint32_t* bst1 = sB1 + cp * BSTRIDE + row * 4;
    const uint32_t* bld0 = sB0 + t4 * BSTRIDE + g * 16 + ng * 8;
    const uint32_t* bld1 = sB1 + t4 * BSTRIDE + g * 16 + ng * 8;

    const float bias00 = s_bias[ob + g];
    const float bias01 = s_bias[ob + g + 8];
    const float bias10 = s_bias[ob + 16 + g];
    const float bias11 = s_bias[ob + 24 + g];

    // ---- prologue ----
    int t = blockIdx.x;
    load_spk(spk0, t, tid);
    __syncthreads();
    dw_tile(spk0, bst0, w0r, w1r, cp, row);
    if (t + GRID < NTILES) load_spk(spk1, t + GRID, tid);
    __syncthreads();

    int buf = 0;
    for (; t < NTILES; t += GRID) {
        const int tn = t + GRID;

        // ---- dw(t+1) into B[buf^1] from spk[buf^1] ----
        if (tn < NTILES)
            dw_tile(buf ? spk0 : spk1, buf ? bst0 : bst1, w0r, w1r, cp, row);

        // ---- GEMM(t) from B[buf] ----
        float acc[2][8][4];
#pragma unroll
        for (int mt = 0; mt < 2; mt++)
#pragma unroll
            for (int nt = 0; nt < 8; nt++)
#pragma unroll
                for (int r = 0; r < 4; r++) acc[mt][nt][r] = 0.f;

        const uint32_t* bld = buf ? bld1 : bld0;
#pragma unroll
        for (int s = 0; s < 8; s++) {
            const uint32_t* bp = bld + (8 * s) * BSTRIDE;
            uint4 u0 = *reinterpret_cast<const uint4*>(bp);
            uint4 u1 = *reinterpret_cast<const uint4*>(bp + 4);
            uint4 u2 = *reinterpret_cast<const uint4*>(bp + 4 * BSTRIDE);
            uint4 u3 = *reinterpret_cast<const uint4*>(bp + 4 * BSTRIDE + 4);
            uint32_t b0[8] = {u0.x, u0.y, u0.z, u0.w, u1.x, u1.y, u1.z, u1.w};
            uint32_t b1[8] = {u2.x, u2.y, u2.z, u2.w, u3.x, u3.y, u3.z, u3.w};
#pragma unroll
            for (int nt = 0; nt < 8; nt++) {
                mma_f16(acc[0][nt][0], acc[0][nt][1], acc[0][nt][2], acc[0][nt][3],
                        af[s][0][0], af[s][0][1], af[s][0][2], af[s][0][3],
                        b0[nt], b1[nt]);
                mma_f16(acc[1][nt][0], acc[1][nt][1], acc[1][nt][2], acc[1][nt][3],
                        af[s][1][0], af[s][1][1], af[s][1][2], af[s][1][3],
                        b0[nt], b1[nt]);
            }
        }

        // ---- prefetch spikes(t+2) into spk[buf] ----
        if (tn + GRID < NTILES)
            load_spk(buf ? spk1 : spk0, tn + GRID, tid);

        // ---- epilogue(t) ----
        {
            const int img = t >> 3, ptile = t & 7;
            float* obase = out + (size_t)img * (COUT * HW) + ptile * 128 + nb + 2 * t4;
#pragma unroll
            for (int mt = 0; mt < 2; mt++) {
                const float blo = (mt == 0) ? bias00 : bias10;
                const float bhi = (mt == 0) ? bias01 : bias11;
                float* r0 = obase + (size_t)(ob + mt * 16 + g) * HW;
#pragma unroll
                for (int nt = 0; nt < 8; nt++) {
                    float2 v0 = make_float2(acc[mt][nt][0] + blo, acc[mt][nt][1] + blo);
                    float2 v1 = make_float2(acc[mt][nt][2] + bhi, acc[mt][nt][3] + bhi);
                    *reinterpret_cast<float2*>(r0 + nt * 8)          = v0;
                    *reinterpret_cast<float2*>(r0 + 8 * HW + nt * 8) = v1;
                }
            }
        }
        __syncthreads();
        buf ^= 1;
    }
}

// ---------------------------------------------------------------------------
// Launcher
// ---------------------------------------------------------------------------
extern "C" void kernel_launch(void* const* d_in, const int* in_sizes, int n_in,
                              void* d_out, int out_size)
{
    const float* x     = (const float*)d_in[0];
    const float* dw_w  = (const float*)d_in[1];
    const float* dw_b  = (const float*)d_in[2];
    const float* pw_w  = (const float*)d_in[3];
    const float* pw_b  = (const float*)d_in[4];
    const float* gamma = (const float*)d_in[5];
    const float* beta  = (const float*)d_in[6];
    const float* rmean = (const float*)d_in[7];
    const float* rvar  = (const float*)d_in[8];
    float* out = (float*)d_out;

    lif_kernel<<<ELEMS_T / (256 * 4), 256>>>(x);

    cudaFuncSetAttribute(fused_mma_kernel,
                         cudaFuncAttributeMaxDynamicSharedMemorySize, SMEM_TOTAL);
    fused_mma_kernel<<<GRID, NTHREADS, SMEM_TOTAL>>>(dw_w, dw_b, pw_w, pw_b,
                                                     gamma, beta, rmean, rvar, out);
}

// round 8
// speedup vs baseline: 3.7467x; 1.1297x over previous
#include <cuda_runtime.h>
#include <cstdint>

#define T_STEPS 16
#define NB      32
#define HH      32
#define WW      32
#define COUT    128
#define HW      (HH*WW)
#define ELEMS_T (NB*128*HH*WW)
#define IMGS    (T_STEPS*NB)
#define NTILES  (IMGS*8)
#define GRID    152
#define NTHREADS 512

// Bit-packed spikes: word (img, h, c) = 32 px of row h, channel c.
__device__ uint32_t g_spk[(size_t)IMGS * 32 * 128];

// ---------------------------------------------------------------------------
// Kernel 1: LIF scan -> bit-packed spikes
// ---------------------------------------------------------------------------
__global__ __launch_bounds__(256) void lif_kernel(const float* __restrict__ x)
{
    const int i = (blockIdx.x * 256 + threadIdx.x) * 4;   // px index, w fastest
    if (i >= ELEMS_T) return;
    const int lane = threadIdx.x & 31;
    const int w0   = i & 31;
    const size_t waddr = ((size_t)(i >> 17)) * 4096
                       + (size_t)((i >> 5) & 31) * 128
                       + (size_t)((i >> 10) & 127);
    float v0 = 0.f, v1 = 0.f, v2 = 0.f, v3 = 0.f;
#pragma unroll
    for (int t = 0; t < T_STEPS; t++) {
        float4 xv = *reinterpret_cast<const float4*>(x + (size_t)t * ELEMS_T + i);
        v0 = v0 + (xv.x - v0) * 0.5f;
        v1 = v1 + (xv.y - v1) * 0.5f;
        v2 = v2 + (xv.z - v2) * 0.5f;
        v3 = v3 + (xv.w - v3) * 0.5f;
        uint32_t nib = (v0 >= 1.0f ? 1u : 0u) | (v1 >= 1.0f ? 2u : 0u)
                     | (v2 >= 1.0f ? 4u : 0u) | (v3 >= 1.0f ? 8u : 0u);
        if (v0 >= 1.0f) v0 = 0.f;
        if (v1 >= 1.0f) v1 = 0.f;
        if (v2 >= 1.0f) v2 = 0.f;
        if (v3 >= 1.0f) v3 = 0.f;
        uint32_t m = nib << w0;
        m |= __shfl_xor_sync(0xFFFFFFFFu, m, 1);
        m |= __shfl_xor_sync(0xFFFFFFFFu, m, 2);
        m |= __shfl_xor_sync(0xFFFFFFFFu, m, 4);
        if ((lane & 7) == 0)
            g_spk[(size_t)t * (NB * 4096) + waddr] = m;
    }
}

// ---------------------------------------------------------------------------
// helpers
// ---------------------------------------------------------------------------
__device__ __forceinline__ uint32_t packh2(float lo, float hi) {
    uint32_t r;
    asm("cvt.rn.f16x2.f32 %0, %1, %2;" : "=r"(r) : "f"(hi), "f"(lo));
    return r;
}
__device__ __forceinline__ void mma_f16(float& c0, float& c1, float& c2, float& c3,
                                        uint32_t a0, uint32_t a1, uint32_t a2, uint32_t a3,
                                        uint32_t b0, uint32_t b1)
{
    asm volatile(
        "mma.sync.aligned.m16n8k16.row.col.f32.f16.f16.f32 "
        "{%0,%1,%2,%3}, {%4,%5,%6,%7}, {%8,%9}, {%0,%1,%2,%3};"
        : "+f"(c0), "+f"(c1), "+f"(c2), "+f"(c3)
        : "r"(a0), "r"(a1), "r"(a2), "r"(a3), "r"(b0), "r"(b1));
}

// ---------------------------------------------------------------------------
// SMEM layout (bytes)
// ---------------------------------------------------------------------------
#define OFF_BIAS  0                       // 128 f32
#define OFF_DWW   512                     // 1152 f32 -> ends 5120
#define OFF_A     5120                    // 2048 uint4 = 32768 -> ends 37888
#define OFF_B0    37888                   // 64 kw x 132-word stride = 33792
#define OFF_B1    71680
#define BSTRIDE   132
#define SMEM_TOTAL 105472

// ---------------------------------------------------------------------------
// Kernel 2: warp-specialized fused dw3x3 (8 producer warps, CUDA cores) +
//           pw1x1+BN GEMM (8 consumer warps, mma.sync fp16)
// ---------------------------------------------------------------------------
__global__ __launch_bounds__(NTHREADS, 1) void fused_ws_kernel(
    const float* __restrict__ dw_w,  const float* __restrict__ dw_b,
    const float* __restrict__ pw_w,  const float* __restrict__ pw_b,
    const float* __restrict__ gamma, const float* __restrict__ beta,
    const float* __restrict__ rmean, const float* __restrict__ rvar,
    float* __restrict__ out)
{
    extern __shared__ unsigned char smem[];
    float*    s_bias = reinterpret_cast<float*>(smem + OFF_BIAS);
    float*    s_dww  = reinterpret_cast<float*>(smem + OFF_DWW);
    uint32_t* s_A    = reinterpret_cast<uint32_t*>(smem + OFF_A);
    uint32_t* sB0    = reinterpret_cast<uint32_t*>(smem + OFF_B0);
    uint32_t* sB1    = reinterpret_cast<uint32_t*>(smem + OFF_B1);

    const int tid = threadIdx.x;
    const int lid = tid & 31;

    // ================= one-time setup =================
    for (int i = tid; i < 1152; i += NTHREADS) s_dww[i] = dw_w[i];
    if (tid < 128) {
        int o = tid;
        float sc = gamma[o] * rsqrtf(rvar[o] + 1e-5f);
        float s = 0.f;
        for (int c = 0; c < 128; c++) s += pw_w[o * 128 + c] * dw_b[c];
        s_bias[o] = beta[o] + sc * (pw_b[o] - rmean[o] + s);
    }
    // A fragments into SMEM: seg = mg*16 + mt*8 + ks, lane uint4; weights sc*pw
    for (int i = tid; i < 2048; i += NTHREADS) {
        int seg  = i >> 5, lane = i & 31;
        int smg  = seg >> 4, smt = (seg >> 3) & 1, sks = seg & 7;
        int sg   = lane >> 2, st4 = lane & 3;
        int o0   = smg * 32 + smt * 16 + sg;
        int o1   = o0 + 8;
        float s0 = gamma[o0] * rsqrtf(rvar[o0] + 1e-5f);
        float s1 = gamma[o1] * rsqrtf(rvar[o1] + 1e-5f);
        const float* w0 = pw_w + o0 * 128;
        const float* w1 = pw_w + o1 * 128;
        int cl = sks * 8 + st4;
        uint4 v;
        v.x = packh2(w0[cl]     * s0, w0[cl + 64] * s0);
        v.y = packh2(w1[cl]     * s1, w1[cl + 64] * s1);
        v.z = packh2(w0[cl + 4] * s0, w0[cl + 68] * s0);
        v.w = packh2(w1[cl + 4] * s1, w1[cl + 68] * s1);
        *reinterpret_cast<uint4*>(s_A + (size_t)i * 4) = v;
    }
    __syncthreads();

    const int t0 = blockIdx.x;

    if (tid < 256) {
        // =====================================================================
        // CONSUMER: GEMM + epilogue (warps 0-7)
        // =====================================================================
        const int wid = tid >> 5;
        const int g   = lid >> 2;
        const int t4  = lid & 3;
        const int mg  = wid & 3;
        const int ng  = wid >> 2;
        const int ob  = mg * 32;
        const int nb  = ng * 64;

        const uint32_t* bld0 = sB0 + t4 * BSTRIDE + g * 16 + ng * 8;
        const uint32_t* bld1 = sB1 + t4 * BSTRIDE + g * 16 + ng * 8;
        const uint32_t* ald  = s_A + (size_t)(mg * 16) * 128 + (size_t)lid * 4;

        const float bias00 = s_bias[ob + g];
        const float bias01 = s_bias[ob + g + 8];
        const float bias10 = s_bias[ob + 16 + g];
        const float bias11 = s_bias[ob + 24 + g];

        __syncthreads();            // matches producer's prologue barrier

        int it = 0;
        for (int t = t0; t < NTILES; t += GRID, ++it) {
            float acc[2][8][4];
#pragma unroll
            for (int mt = 0; mt < 2; mt++)
#pragma unroll
                for (int nt = 0; nt < 8; nt++)
#pragma unroll
                    for (int r = 0; r < 4; r++) acc[mt][nt][r] = 0.f;

            const uint32_t* bld = (it & 1) ? bld1 : bld0;
#pragma unroll
            for (int s = 0; s < 8; s++) {
                const uint32_t* bp = bld + (8 * s) * BSTRIDE;
                uint4 u0 = *reinterpret_cast<const uint4*>(bp);
                uint4 u1 = *reinterpret_cast<const uint4*>(bp + 4);
                uint4 u2 = *reinterpret_cast<const uint4*>(bp + 4 * BSTRIDE);
                uint4 u3 = *reinterpret_cast<const uint4*>(bp + 4 * BSTRIDE + 4);
                uint4 a0 = *reinterpret_cast<const uint4*>(ald + (size_t)s * 128);
                uint4 a1 = *reinterpret_cast<const uint4*>(ald + (size_t)(s + 8) * 128);
                uint32_t b0[8] = {u0.x, u0.y, u0.z, u0.w, u1.x, u1.y, u1.z, u1.w};
                uint32_t b1[8] = {u2.x, u2.y, u2.z, u2.w, u3.x, u3.y, u3.z, u3.w};
#pragma unroll
                for (int nt = 0; nt < 8; nt++) {
                    mma_f16(acc[0][nt][0], acc[0][nt][1], acc[0][nt][2], acc[0][nt][3],
                            a0.x, a0.y, a0.z, a0.w, b0[nt], b1[nt]);
                    mma_f16(acc[1][nt][0], acc[1][nt][1], acc[1][nt][2], acc[1][nt][3],
                            a1.x, a1.y, a1.z, a1.w, b0[nt], b1[nt]);
                }
            }

            // epilogue
            {
                const int img = t >> 3, ptile = t & 7;
                float* obase = out + (size_t)img * (COUT * HW) + ptile * 128 + nb + 2 * t4;
#pragma unroll
                for (int mt = 0; mt < 2; mt++) {
                    const float blo = (mt == 0) ? bias00 : bias10;
                    const float bhi = (mt == 0) ? bias01 : bias11;
                    float* r0 = obase + (size_t)(ob + mt * 16 + g) * HW;
#pragma unroll
                    for (int nt = 0; nt < 8; nt++) {
                        float2 v0 = make_float2(acc[mt][nt][0] + blo, acc[mt][nt][1] + blo);
                        float2 v1 = make_float2(acc[mt][nt][2] + bhi, acc[mt][nt][3] + bhi);
                        *reinterpret_cast<float2*>(r0 + nt * 8)          = v0;
                        *reinterpret_cast<float2*>(r0 + 8 * HW + nt * 8) = v1;
                    }
                }
            }
            __syncthreads();
        }
    } else {
        // =====================================================================
        // PRODUCER: depthwise 3x3 (warps 8-15)
        // =====================================================================
        const int local = tid - 256;
        const int cp    = local & 63;
        const int row   = local >> 6;          // output row within tile (0..3)

        float w0r[9], w1r[9];
#pragma unroll
        for (int i = 0; i < 9; i++) {
            w0r[i] = s_dww[cp * 9 + i];
            w1r[i] = s_dww[(cp + 64) * 9 + i];
        }
        uint32_t* bst0 = sB0 + cp * BSTRIDE + row * 4;
        uint32_t* bst1 = sB1 + cp * BSTRIDE + row * 4;

        // spike loader: 6 words (3 rows x 2 channels) for tile t
        auto ldspk = [&](int t, uint32_t (&sw)[6]) {
            const int img = t >> 3, r0 = (t & 7) * 4;
            const uint32_t* gg = g_spk + (size_t)img * 4096;
#pragma unroll
            for (int rr = 0; rr < 3; rr++) {
                int gr = r0 - 1 + row + rr;
                bool ok = (unsigned)gr < 32u;
                sw[rr]     = ok ? gg[gr * 128 + cp]      : 0u;
                sw[rr + 3] = ok ? gg[gr * 128 + cp + 64] : 0u;
            }
        };
        // dw compute from sw regs into B buffer (exact 0/1 spike values)
        auto dwcomp = [&](const uint32_t (&sw)[6], uint32_t* bst) {
            float o0[32], o1[32];
#pragma unroll
            for (int i = 0; i < 32; i++) { o0[i] = 0.f; o1[i] = 0.f; }
#pragma unroll
            for (int h = 0; h < 2; h++) {
                const float* w = h ? w1r : w0r;
                float* o = h ? o1 : o0;
#pragma unroll
                for (int rr = 0; rr < 3; rr++) {
                    uint32_t wd = sw[h * 3 + rr];
                    float f[34];
                    f[0] = 0.f; f[33] = 0.f;
#pragma unroll
                    for (int j = 1; j <= 32; j++)
                        f[j] = __int_as_float((int)(((wd >> (j - 1)) & 1u) * 0x3f800000u));
                    const float wa = w[rr * 3], wb = w[rr * 3 + 1], wc = w[rr * 3 + 2];
#pragma unroll
                    for (int col = 0; col < 32; col++)
                        o[col] += wa * f[col] + wb * f[col + 1] + wc * f[col + 2];
                }
            }
#pragma unroll
            for (int j = 0; j < 8; j++) {
                uint4 v;
                v.x = packh2(o0[j],      o1[j]);
                v.y = packh2(o0[j + 8],  o1[j + 8]);
                v.z = packh2(o0[j + 16], o1[j + 16]);
                v.w = packh2(o0[j + 24], o1[j + 24]);
                *reinterpret_cast<uint4*>(bst + j * 16) = v;
            }
        };

        // prologue: produce B0 for t0, prefetch spikes for t0+GRID
        uint32_t sw[6], swn[6];
        ldspk(t0, sw);
        dwcomp(sw, bst0);
        if (t0 + GRID < NTILES) ldspk(t0 + GRID, swn);
        __syncthreads();

        int it = 0;
        for (int t = t0; t < NTILES; t += GRID, ++it) {
            const int tn = t + GRID;
            if (tn < NTILES) {
#pragma unroll
                for (int k = 0; k < 6; k++) sw[k] = swn[k];
                dwcomp(sw, (it & 1) ? bst0 : bst1);       // B[(it+1)&1]
                if (tn + GRID < NTILES) ldspk(tn + GRID, swn);
            }
            __syncthreads();
        }
    }
}

// ---------------------------------------------------------------------------
// Launcher
// ---------------------------------------------------------------------------
extern "C" void kernel_launch(void* const* d_in, const int* in_sizes, int n_in,
                              void* d_out, int out_size)
{
    const float* x     = (const float*)d_in[0];
    const float* dw_w  = (const float*)d_in[1];
    const float* dw_b  = (const float*)d_in[2];
    const float* pw_w  = (const float*)d_in[3];
    const float* pw_b  = (const float*)d_in[4];
    const float* gamma = (const float*)d_in[5];
    const float* beta  = (const float*)d_in[6];
    const float* rmean = (const float*)d_in[7];
    const float* rvar  = (const float*)d_in[8];
    float* out = (float*)d_out;

    lif_kernel<<<ELEMS_T / (256 * 4), 256>>>(x);

    cudaFuncSetAttribute(fused_ws_kernel,
                         cudaFuncAttributeMaxDynamicSharedMemorySize, SMEM_TOTAL);
    fused_ws_kernel<<<GRID, NTHREADS, SMEM_TOTAL>>>(dw_w, dw_b, pw_w, pw_b,
                                                    gamma, beta, rmean, rvar, out);
}

// round 9
// speedup vs baseline: 3.9707x; 1.0598x over previous
#include <cuda_runtime.h>
#include <cstdint>

#define T_STEPS 16
#define NB      32
#define HH      32
#define WW      32
#define COUT    128
#define HW      (HH*WW)
#define ELEMS_T (NB*128*HH*WW)
#define IMGS    (T_STEPS*NB)
#define NTILES  (IMGS*8)
#define GRID    152
#define NTHREADS 512

// Bit-packed spikes: word (img, h, c) = 32 px of row h, channel c.
__device__ uint32_t g_spk[(size_t)IMGS * 32 * 128];

// ---------------------------------------------------------------------------
// Kernel 1: LIF scan -> bit-packed spikes (streaming loads)
// ---------------------------------------------------------------------------
__global__ __launch_bounds__(256) void lif_kernel(const float* __restrict__ x)
{
    const int i = (blockIdx.x * 256 + threadIdx.x) * 4;   // px index, w fastest
    if (i >= ELEMS_T) return;
    const int lane = threadIdx.x & 31;
    const int w0   = i & 31;
    const size_t waddr = ((size_t)(i >> 17)) * 4096
                       + (size_t)((i >> 5) & 31) * 128
                       + (size_t)((i >> 10) & 127);
    float v0 = 0.f, v1 = 0.f, v2 = 0.f, v3 = 0.f;
#pragma unroll
    for (int t = 0; t < T_STEPS; t++) {
        float4 xv = __ldcs(reinterpret_cast<const float4*>(x + (size_t)t * ELEMS_T + i));
        v0 = v0 + (xv.x - v0) * 0.5f;
        v1 = v1 + (xv.y - v1) * 0.5f;
        v2 = v2 + (xv.z - v2) * 0.5f;
        v3 = v3 + (xv.w - v3) * 0.5f;
        uint32_t nib = (v0 >= 1.0f ? 1u : 0u) | (v1 >= 1.0f ? 2u : 0u)
                     | (v2 >= 1.0f ? 4u : 0u) | (v3 >= 1.0f ? 8u : 0u);
        if (v0 >= 1.0f) v0 = 0.f;
        if (v1 >= 1.0f) v1 = 0.f;
        if (v2 >= 1.0f) v2 = 0.f;
        if (v3 >= 1.0f) v3 = 0.f;
        uint32_t m = nib << w0;
        m |= __shfl_xor_sync(0xFFFFFFFFu, m, 1);
        m |= __shfl_xor_sync(0xFFFFFFFFu, m, 2);
        m |= __shfl_xor_sync(0xFFFFFFFFu, m, 4);
        if ((lane & 7) == 0)
            __stcg(&g_spk[(size_t)t * (NB * 4096) + waddr], m);
    }
}

// ---------------------------------------------------------------------------
// helpers
// ---------------------------------------------------------------------------
__device__ __forceinline__ uint32_t packh2(float lo, float hi) {
    uint32_t r;
    asm("cvt.rn.f16x2.f32 %0, %1, %2;" : "=r"(r) : "f"(hi), "f"(lo));
    return r;
}
__device__ __forceinline__ void mma_f16(float& c0, float& c1, float& c2, float& c3,
                                        uint32_t a0, uint32_t a1, uint32_t a2, uint32_t a3,
                                        uint32_t b0, uint32_t b1)
{
    asm volatile(
        "mma.sync.aligned.m16n8k16.row.col.f32.f16.f16.f32 "
        "{%0,%1,%2,%3}, {%4,%5,%6,%7}, {%8,%9}, {%0,%1,%2,%3};"
        : "+f"(c0), "+f"(c1), "+f"(c2), "+f"(c3)
        : "r"(a0), "r"(a1), "r"(a2), "r"(a3), "r"(b0), "r"(b1));
}
#define BAR_SYNC(id)   asm volatile("bar.sync %0, %1;"   :: "r"(id), "r"(NTHREADS) : "memory")
#define BAR_ARRIVE(id) asm volatile("bar.arrive %0, %1;" :: "r"(id), "r"(NTHREADS) : "memory")

// ---------------------------------------------------------------------------
// SMEM layout (bytes)
// ---------------------------------------------------------------------------
#define OFF_BIAS  0                       // 128 f32
#define OFF_DWW   512                     // 1152 f32 -> ends 5120
#define OFF_A     5120                    // 2048 uint4 = 32768 -> ends 37888
#define OFF_B0    37888                   // 64 kw x 132-word stride = 33792
#define OFF_B1    71680
#define BSTRIDE   132
#define SMEM_TOTAL 105472

// ---------------------------------------------------------------------------
// Kernel 2: warp-specialized fused dw3x3 (producer warps 8-15) +
//           pw1x1+BN GEMM (consumer warps 0-7), named-barrier pipeline
// barriers: full[b] = 1+b (producer arrives, consumer syncs)
//           empty[b] = 3+b (consumer arrives, producer syncs)
// ---------------------------------------------------------------------------
__global__ __launch_bounds__(NTHREADS, 1) void fused_ws_kernel(
    const float* __restrict__ dw_w,  const float* __restrict__ dw_b,
    const float* __restrict__ pw_w,  const float* __restrict__ pw_b,
    const float* __restrict__ gamma, const float* __restrict__ beta,
    const float* __restrict__ rmean, const float* __restrict__ rvar,
    float* __restrict__ out)
{
    extern __shared__ unsigned char smem[];
    float*    s_bias = reinterpret_cast<float*>(smem + OFF_BIAS);
    float*    s_dww  = reinterpret_cast<float*>(smem + OFF_DWW);
    uint32_t* s_A    = reinterpret_cast<uint32_t*>(smem + OFF_A);
    uint32_t* sB0    = reinterpret_cast<uint32_t*>(smem + OFF_B0);
    uint32_t* sB1    = reinterpret_cast<uint32_t*>(smem + OFF_B1);

    const int tid = threadIdx.x;
    const int lid = tid & 31;

    // ================= one-time setup =================
    for (int i = tid; i < 1152; i += NTHREADS) s_dww[i] = dw_w[i];
    if (tid < 128) {
        int o = tid;
        float sc = gamma[o] * rsqrtf(rvar[o] + 1e-5f);
        float s = 0.f;
        for (int c = 0; c < 128; c++) s += pw_w[o * 128 + c] * dw_b[c];
        s_bias[o] = beta[o] + sc * (pw_b[o] - rmean[o] + s);
    }
    for (int i = tid; i < 2048; i += NTHREADS) {
        int seg  = i >> 5, lane = i & 31;
        int smg  = seg >> 4, smt = (seg >> 3) & 1, sks = seg & 7;
        int sg   = lane >> 2, st4 = lane & 3;
        int o0   = smg * 32 + smt * 16 + sg;
        int o1   = o0 + 8;
        float s0 = gamma[o0] * rsqrtf(rvar[o0] + 1e-5f);
        float s1 = gamma[o1] * rsqrtf(rvar[o1] + 1e-5f);
        const float* w0 = pw_w + o0 * 128;
        const float* w1 = pw_w + o1 * 128;
        int cl = sks * 8 + st4;
        uint4 v;
        v.x = packh2(w0[cl]     * s0, w0[cl + 64] * s0);
        v.y = packh2(w1[cl]     * s1, w1[cl + 64] * s1);
        v.z = packh2(w0[cl + 4] * s0, w0[cl + 68] * s0);
        v.w = packh2(w1[cl + 4] * s1, w1[cl + 68] * s1);
        *reinterpret_cast<uint4*>(s_A + (size_t)i * 4) = v;
    }
    __syncthreads();

    const int t0 = blockIdx.x;

    if (tid < 256) {
        // =====================================================================
        // CONSUMER: GEMM + epilogue (warps 0-7)
        // =====================================================================
        const int wid = tid >> 5;
        const int g   = lid >> 2;
        const int t4  = lid & 3;
        const int mg  = wid & 3;
        const int ng  = wid >> 2;
        const int ob  = mg * 32;
        const int nb  = ng * 64;

        const uint32_t* bld0 = sB0 + t4 * BSTRIDE + g * 16 + ng * 8;
        const uint32_t* bld1 = sB1 + t4 * BSTRIDE + g * 16 + ng * 8;
        const uint32_t* ald  = s_A + (size_t)(mg * 16) * 128 + (size_t)lid * 4;

        const float bias00 = s_bias[ob + g];
        const float bias01 = s_bias[ob + g + 8];
        const float bias10 = s_bias[ob + 16 + g];
        const float bias11 = s_bias[ob + 24 + g];

        int it = 0;
        for (int t = t0; t < NTILES; t += GRID, ++it) {
            const int b = it & 1;
            BAR_SYNC(1 + b);                      // wait B[b] full

            float acc[2][8][4];
#pragma unroll
            for (int mt = 0; mt < 2; mt++)
#pragma unroll
                for (int nt = 0; nt < 8; nt++)
#pragma unroll
                    for (int r = 0; r < 4; r++) acc[mt][nt][r] = 0.f;

            const uint32_t* bld = b ? bld1 : bld0;
#pragma unroll
            for (int s = 0; s < 8; s++) {
                const uint32_t* bp = bld + (8 * s) * BSTRIDE;
                uint4 u0 = *reinterpret_cast<const uint4*>(bp);
                uint4 u1 = *reinterpret_cast<const uint4*>(bp + 4);
                uint4 u2 = *reinterpret_cast<const uint4*>(bp + 4 * BSTRIDE);
                uint4 u3 = *reinterpret_cast<const uint4*>(bp + 4 * BSTRIDE + 4);
                uint4 a0 = *reinterpret_cast<const uint4*>(ald + (size_t)s * 128);
                uint4 a1 = *reinterpret_cast<const uint4*>(ald + (size_t)(s + 8) * 128);
                uint32_t b0[8] = {u0.x, u0.y, u0.z, u0.w, u1.x, u1.y, u1.z, u1.w};
                uint32_t b1[8] = {u2.x, u2.y, u2.z, u2.w, u3.x, u3.y, u3.z, u3.w};
#pragma unroll
                for (int nt = 0; nt < 8; nt++) {
                    mma_f16(acc[0][nt][0], acc[0][nt][1], acc[0][nt][2], acc[0][nt][3],
                            a0.x, a0.y, a0.z, a0.w, b0[nt], b1[nt]);
                    mma_f16(acc[1][nt][0], acc[1][nt][1], acc[1][nt][2], acc[1][nt][3],
                            a1.x, a1.y, a1.z, a1.w, b0[nt], b1[nt]);
                }
            }
            BAR_ARRIVE(3 + b);                    // release B[b] BEFORE stores

            // epilogue (overlaps producer's next dw)
            {
                const int img = t >> 3, ptile = t & 7;
                float* obase = out + (size_t)img * (COUT * HW) + ptile * 128 + nb + 2 * t4;
#pragma unroll
                for (int mt = 0; mt < 2; mt++) {
                    const float blo = (mt == 0) ? bias00 : bias10;
                    const float bhi = (mt == 0) ? bias01 : bias11;
                    float* r0 = obase + (size_t)(ob + mt * 16 + g) * HW;
#pragma unroll
                    for (int nt = 0; nt < 8; nt++) {
                        float2 v0 = make_float2(acc[mt][nt][0] + blo, acc[mt][nt][1] + blo);
                        float2 v1 = make_float2(acc[mt][nt][2] + bhi, acc[mt][nt][3] + bhi);
                        *reinterpret_cast<float2*>(r0 + nt * 8)          = v0;
                        *reinterpret_cast<float2*>(r0 + 8 * HW + nt * 8) = v1;
                    }
                }
            }
        }
    } else {
        // =====================================================================
        // PRODUCER: depthwise 3x3 (warps 8-15)
        // =====================================================================
        const int local = tid - 256;
        const int cp    = local & 63;
        const int row   = local >> 6;

        float w0r[9], w1r[9];
#pragma unroll
        for (int i = 0; i < 9; i++) {
            w0r[i] = s_dww[cp * 9 + i];
            w1r[i] = s_dww[(cp + 64) * 9 + i];
        }
        uint32_t* bst0 = sB0 + cp * BSTRIDE + row * 4;
        uint32_t* bst1 = sB1 + cp * BSTRIDE + row * 4;

        auto ldspk = [&](int t, uint32_t (&sw)[6]) {
            const int img = t >> 3, r0 = (t & 7) * 4;
            const uint32_t* gg = g_spk + (size_t)img * 4096;
#pragma unroll
            for (int rr = 0; rr < 3; rr++) {
                int gr = r0 - 1 + row + rr;
                bool ok = (unsigned)gr < 32u;
                sw[rr]     = ok ? gg[gr * 128 + cp]      : 0u;
                sw[rr + 3] = ok ? gg[gr * 128 + cp + 64] : 0u;
            }
        };
        auto dwcomp = [&](const uint32_t (&sw)[6], uint32_t* bst) {
            float o0[32], o1[32];
#pragma unroll
            for (int i = 0; i < 32; i++) { o0[i] = 0.f; o1[i] = 0.f; }
#pragma unroll
            for (int h = 0; h < 2; h++) {
                const float* w = h ? w1r : w0r;
                float* o = h ? o1 : o0;
#pragma unroll
                for (int rr = 0; rr < 3; rr++) {
                    uint32_t wd = sw[h * 3 + rr];
                    float f[34];
                    f[0] = 0.f; f[33] = 0.f;
#pragma unroll
                    for (int j = 1; j <= 32; j++)
                        f[j] = __int_as_float((int)(((wd >> (j - 1)) & 1u) * 0x3f800000u));
                    const float wa = w[rr * 3], wb = w[rr * 3 + 1], wc = w[rr * 3 + 2];
#pragma unroll
                    for (int col = 0; col < 32; col++)
                        o[col] += wa * f[col] + wb * f[col + 1] + wc * f[col + 2];
                }
            }
#pragma unroll
            for (int j = 0; j < 8; j++) {
                uint4 v;
                v.x = packh2(o0[j],      o1[j]);
                v.y = packh2(o0[j + 8],  o1[j + 8]);
                v.z = packh2(o0[j + 16], o1[j + 16]);
                v.w = packh2(o0[j + 24], o1[j + 24]);
                *reinterpret_cast<uint4*>(bst + j * 16) = v;
            }
        };

        uint32_t sw[6];
        ldspk(t0, sw);

        int it = 0;
        for (int t = t0; t < NTILES; t += GRID, ++it) {
            const int b = it & 1;
            if (it >= 2) BAR_SYNC(3 + b);         // wait B[b] empty
            dwcomp(sw, b ? bst1 : bst0);
            BAR_ARRIVE(1 + b);                    // signal B[b] full
            if (t + GRID < NTILES) ldspk(t + GRID, sw);
        }
    }
}

// ---------------------------------------------------------------------------
// Launcher
// ---------------------------------------------------------------------------
extern "C" void kernel_launch(void* const* d_in, const int* in_sizes, int n_in,
                              void* d_out, int out_size)
{
    const float* x     = (const float*)d_in[0];
    const float* dw_w  = (const float*)d_in[1];
    const float* dw_b  = (const float*)d_in[2];
    const float* pw_w  = (const float*)d_in[3];
    const float* pw_b  = (const float*)d_in[4];
    const float* gamma = (const float*)d_in[5];
    const float* beta  = (const float*)d_in[6];
    const float* rmean = (const float*)d_in[7];
    const float* rvar  = (const float*)d_in[8];
    float* out = (float*)d_out;

    lif_kernel<<<ELEMS_T / (256 * 4), 256>>>(x);

    cudaFuncSetAttribute(fused_ws_kernel,
                         cudaFuncAttributeMaxDynamicSharedMemorySize, SMEM_TOTAL);
    fused_ws_kernel<<<GRID, NTHREADS, SMEM_TOTAL>>>(dw_w, dw_b, pw_w, pw_b,
                                                    gamma, beta, rmean, rvar, out);
}

// round 10
// speedup vs baseline: 3.9915x; 1.0052x over previous
#include <cuda_runtime.h>
#include <cstdint>

#define T_STEPS 16
#define NB      32
#define HH      32
#define WW      32
#define COUT    128
#define HW      (HH*WW)
#define ELEMS_T (NB*128*HH*WW)
#define IMGS    (T_STEPS*NB)
#define NTILES  (IMGS*8)
#define GRID    152
#define NTHREADS 512

// Bit-packed spikes: word (img, h, c) = 32 px of row h, channel c.
__device__ uint32_t g_spk[(size_t)IMGS * 32 * 128];

// ---------------------------------------------------------------------------
// Kernel 1: LIF scan -> bit-packed spikes (explicit MLP=16 preload)
// ---------------------------------------------------------------------------
__global__ __launch_bounds__(256) void lif_kernel(const float* __restrict__ x)
{
    const int i = (blockIdx.x * 256 + threadIdx.x) * 4;   // px index, w fastest
    if (i >= ELEMS_T) return;
    const int lane = threadIdx.x & 31;
    const int w0   = i & 31;
    const size_t waddr = ((size_t)(i >> 17)) * 4096
                       + (size_t)((i >> 5) & 31) * 128
                       + (size_t)((i >> 10) & 127);
    float4 xv[T_STEPS];
#pragma unroll
    for (int t = 0; t < T_STEPS; t++)
        xv[t] = __ldcs(reinterpret_cast<const float4*>(x + (size_t)t * ELEMS_T + i));

    float v0 = 0.f, v1 = 0.f, v2 = 0.f, v3 = 0.f;
#pragma unroll
    for (int t = 0; t < T_STEPS; t++) {
        v0 = v0 + (xv[t].x - v0) * 0.5f;
        v1 = v1 + (xv[t].y - v1) * 0.5f;
        v2 = v2 + (xv[t].z - v2) * 0.5f;
        v3 = v3 + (xv[t].w - v3) * 0.5f;
        uint32_t nib = (v0 >= 1.0f ? 1u : 0u) | (v1 >= 1.0f ? 2u : 0u)
                     | (v2 >= 1.0f ? 4u : 0u) | (v3 >= 1.0f ? 8u : 0u);
        if (v0 >= 1.0f) v0 = 0.f;
        if (v1 >= 1.0f) v1 = 0.f;
        if (v2 >= 1.0f) v2 = 0.f;
        if (v3 >= 1.0f) v3 = 0.f;
        uint32_t m = nib << w0;
        m |= __shfl_xor_sync(0xFFFFFFFFu, m, 1);
        m |= __shfl_xor_sync(0xFFFFFFFFu, m, 2);
        m |= __shfl_xor_sync(0xFFFFFFFFu, m, 4);
        if ((lane & 7) == 0)
            __stcg(&g_spk[(size_t)t * (NB * 4096) + waddr], m);
    }
}

// ---------------------------------------------------------------------------
// helpers
// ---------------------------------------------------------------------------
typedef unsigned long long u64;
__device__ __forceinline__ uint32_t packh2(float lo, float hi) {
    uint32_t r;
    asm("cvt.rn.f16x2.f32 %0, %1, %2;" : "=r"(r) : "f"(hi), "f"(lo));
    return r;
}
__device__ __forceinline__ u64 pk2(float lo, float hi) {
    u64 r; asm("mov.b64 %0, {%1, %2};" : "=l"(r) : "f"(lo), "f"(hi)); return r;
}
__device__ __forceinline__ void upk2(float& lo, float& hi, u64 v) {
    asm("mov.b64 {%0, %1}, %2;" : "=f"(lo), "=f"(hi) : "l"(v));
}
__device__ __forceinline__ void ffma2(u64& d, u64 a, u64 b) {
    asm("fma.rn.f32x2 %0, %1, %2, %0;" : "+l"(d) : "l"(a), "l"(b));
}
__device__ __forceinline__ float bitf(uint32_t wd, int i) {
    return (wd & (1u << i)) ? 1.0f : 0.0f;
}
__device__ __forceinline__ void mma_f16(float& c0, float& c1, float& c2, float& c3,
                                        uint32_t a0, uint32_t a1, uint32_t a2, uint32_t a3,
                                        uint32_t b0, uint32_t b1)
{
    asm volatile(
        "mma.sync.aligned.m16n8k16.row.col.f32.f16.f16.f32 "
        "{%0,%1,%2,%3}, {%4,%5,%6,%7}, {%8,%9}, {%0,%1,%2,%3};"
        : "+f"(c0), "+f"(c1), "+f"(c2), "+f"(c3)
        : "r"(a0), "r"(a1), "r"(a2), "r"(a3), "r"(b0), "r"(b1));
}
__device__ __forceinline__ void stcs2(float* p, float a, float b) {
    float2 v = make_float2(a, b);
    __stcs(reinterpret_cast<float2*>(p), v);
}
#define BAR_SYNC(id)   asm volatile("bar.sync %0, %1;"   :: "r"(id), "r"(NTHREADS) : "memory")
#define BAR_ARRIVE(id) asm volatile("bar.arrive %0, %1;" :: "r"(id), "r"(NTHREADS) : "memory")

// ---------------------------------------------------------------------------
// SMEM layout (bytes)
// ---------------------------------------------------------------------------
#define OFF_BIAS  0                       // 128 f32
#define OFF_DWW   512                     // 1152 f32 -> ends 5120
#define OFF_A     5120                    // 2048 uint4 = 32768 -> ends 37888
#define OFF_B0    37888                   // 64 kw x 132-word stride = 33792
#define OFF_B1    71680
#define BSTRIDE   132
#define SMEM_TOTAL 105472

// ---------------------------------------------------------------------------
// Kernel 2: warp-specialized fused dw3x3 (producer warps 8-15, FFMA2) +
//           pw1x1+BN GEMM (consumer warps 0-7, mma.sync fp16)
// ---------------------------------------------------------------------------
__global__ __launch_bounds__(NTHREADS, 1) void fused_ws_kernel(
    const float* __restrict__ dw_w,  const float* __restrict__ dw_b,
    const float* __restrict__ pw_w,  const float* __restrict__ pw_b,
    const float* __restrict__ gamma, const float* __restrict__ beta,
    const float* __restrict__ rmean, const float* __restrict__ rvar,
    float* __restrict__ out)
{
    extern __shared__ unsigned char smem[];
    float*    s_bias = reinterpret_cast<float*>(smem + OFF_BIAS);
    float*    s_dww  = reinterpret_cast<float*>(smem + OFF_DWW);
    uint32_t* s_A    = reinterpret_cast<uint32_t*>(smem + OFF_A);
    uint32_t* sB0    = reinterpret_cast<uint32_t*>(smem + OFF_B0);
    uint32_t* sB1    = reinterpret_cast<uint32_t*>(smem + OFF_B1);

    const int tid = threadIdx.x;
    const int lid = tid & 31;

    // ================= one-time setup =================
    for (int i = tid; i < 1152; i += NTHREADS) s_dww[i] = dw_w[i];
    if (tid < 128) {
        int o = tid;
        float sc = gamma[o] * rsqrtf(rvar[o] + 1e-5f);
        float s = 0.f;
        for (int c = 0; c < 128; c++) s += pw_w[o * 128 + c] * dw_b[c];
        s_bias[o] = beta[o] + sc * (pw_b[o] - rmean[o] + s);
    }
    for (int i = tid; i < 2048; i += NTHREADS) {
        int seg  = i >> 5, lane = i & 31;
        int smg  = seg >> 4, smt = (seg >> 3) & 1, sks = seg & 7;
        int sg   = lane >> 2, st4 = lane & 3;
        int o0   = smg * 32 + smt * 16 + sg;
        int o1   = o0 + 8;
        float s0 = gamma[o0] * rsqrtf(rvar[o0] + 1e-5f);
        float s1 = gamma[o1] * rsqrtf(rvar[o1] + 1e-5f);
        const float* w0 = pw_w + o0 * 128;
        const float* w1 = pw_w + o1 * 128;
        int cl = sks * 8 + st4;
        uint4 v;
        v.x = packh2(w0[cl]     * s0, w0[cl + 64] * s0);
        v.y = packh2(w1[cl]     * s1, w1[cl + 64] * s1);
        v.z = packh2(w0[cl + 4] * s0, w0[cl + 68] * s0);
        v.w = packh2(w1[cl + 4] * s1, w1[cl + 68] * s1);
        *reinterpret_cast<uint4*>(s_A + (size_t)i * 4) = v;
    }
    __syncthreads();

    const int t0 = blockIdx.x;

    if (tid < 256) {
        // =====================================================================
        // CONSUMER: GEMM + epilogue (warps 0-7)
        // =====================================================================
        const int wid = tid >> 5;
        const int g   = lid >> 2;
        const int t4  = lid & 3;
        const int mg  = wid & 3;
        const int ng  = wid >> 2;
        const int ob  = mg * 32;
        const int nb  = ng * 64;

        const uint32_t* bld0 = sB0 + t4 * BSTRIDE + g * 16 + ng * 8;
        const uint32_t* bld1 = sB1 + t4 * BSTRIDE + g * 16 + ng * 8;
        const uint32_t* ald  = s_A + (size_t)(mg * 16) * 128 + (size_t)lid * 4;

        const float bias00 = s_bias[ob + g];
        const float bias01 = s_bias[ob + g + 8];
        const float bias10 = s_bias[ob + 16 + g];
        const float bias11 = s_bias[ob + 24 + g];

        int it = 0;
        for (int t = t0; t < NTILES; t += GRID, ++it) {
            const int b = it & 1;
            BAR_SYNC(1 + b);                      // wait B[b] full

            float acc[2][8][4];
#pragma unroll
            for (int mt = 0; mt < 2; mt++)
#pragma unroll
                for (int nt = 0; nt < 8; nt++)
#pragma unroll
                    for (int r = 0; r < 4; r++) acc[mt][nt][r] = 0.f;

            const uint32_t* bld = b ? bld1 : bld0;
#pragma unroll
            for (int s = 0; s < 8; s++) {
                const uint32_t* bp = bld + (8 * s) * BSTRIDE;
                uint4 u0 = *reinterpret_cast<const uint4*>(bp);
                uint4 u1 = *reinterpret_cast<const uint4*>(bp + 4);
                uint4 u2 = *reinterpret_cast<const uint4*>(bp + 4 * BSTRIDE);
                uint4 u3 = *reinterpret_cast<const uint4*>(bp + 4 * BSTRIDE + 4);
                uint4 a0 = *reinterpret_cast<const uint4*>(ald + (size_t)s * 128);
                uint4 a1 = *reinterpret_cast<const uint4*>(ald + (size_t)(s + 8) * 128);
                uint32_t b0[8] = {u0.x, u0.y, u0.z, u0.w, u1.x, u1.y, u1.z, u1.w};
                uint32_t b1[8] = {u2.x, u2.y, u2.z, u2.w, u3.x, u3.y, u3.z, u3.w};
#pragma unroll
                for (int nt = 0; nt < 8; nt++) {
                    mma_f16(acc[0][nt][0], acc[0][nt][1], acc[0][nt][2], acc[0][nt][3],
                            a0.x, a0.y, a0.z, a0.w, b0[nt], b1[nt]);
                    mma_f16(acc[1][nt][0], acc[1][nt][1], acc[1][nt][2], acc[1][nt][3],
                            a1.x, a1.y, a1.z, a1.w, b0[nt], b1[nt]);
                }
            }
            BAR_ARRIVE(3 + b);                    // release B[b] BEFORE stores

            // epilogue (overlaps producer's next dw)
            {
                const int img = t >> 3, ptile = t & 7;
                float* obase = out + (size_t)img * (COUT * HW) + ptile * 128 + nb + 2 * t4;
#pragma unroll
                for (int mt = 0; mt < 2; mt++) {
                    const float blo = (mt == 0) ? bias00 : bias10;
                    const float bhi = (mt == 0) ? bias01 : bias11;
                    float* r0 = obase + (size_t)(ob + mt * 16 + g) * HW;
#pragma unroll
                    for (int nt = 0; nt < 8; nt++) {
                        stcs2(r0 + nt * 8,          acc[mt][nt][0] + blo, acc[mt][nt][1] + blo);
                        stcs2(r0 + 8 * HW + nt * 8, acc[mt][nt][2] + bhi, acc[mt][nt][3] + bhi);
                    }
                }
            }
        }
    } else {
        // =====================================================================
        // PRODUCER: depthwise 3x3 via packed f32x2 FFMA (warps 8-15)
        // column pairing (k, k+16): O[k] = (o[k], o[k+16])
        // =====================================================================
        const int local = tid - 256;
        const int cp    = local & 63;
        const int row   = local >> 6;

        float w0r[9], w1r[9];
#pragma unroll
        for (int i = 0; i < 9; i++) {
            w0r[i] = s_dww[cp * 9 + i];
            w1r[i] = s_dww[(cp + 64) * 9 + i];
        }
        uint32_t* bst0 = sB0 + cp * BSTRIDE + row * 4;
        uint32_t* bst1 = sB1 + cp * BSTRIDE + row * 4;

        auto ldspk = [&](int t, uint32_t (&sw)[6]) {
            const int img = t >> 3, r0 = (t & 7) * 4;
            const uint32_t* gg = g_spk + (size_t)img * 4096;
#pragma unroll
            for (int rr = 0; rr < 3; rr++) {
                int gr = r0 - 1 + row + rr;
                bool ok = (unsigned)gr < 32u;
                sw[rr]     = ok ? gg[gr * 128 + cp]      : 0u;
                sw[rr + 3] = ok ? gg[gr * 128 + cp + 64] : 0u;
            }
        };
        auto dwcomp = [&](const uint32_t (&sw)[6], uint32_t* bst) {
            u64 O0[16], O1[16];
#pragma unroll
            for (int i = 0; i < 16; i++) { O0[i] = 0ull; O1[i] = 0ull; }
#pragma unroll
            for (int h = 0; h < 2; h++) {
                const float* w = h ? w1r : w0r;
                u64* O = h ? O1 : O0;
#pragma unroll
                for (int rr = 0; rr < 3; rr++) {
                    const uint32_t wd = sw[h * 3 + rr];
                    const u64 wa2 = pk2(w[rr * 3],     w[rr * 3]);
                    const u64 wb2 = pk2(w[rr * 3 + 1], w[rr * 3 + 1]);
                    const u64 wc2 = pk2(w[rr * 3 + 2], w[rr * 3 + 2]);
                    // rolling window of packed operands P[j] = (p[j-1], p[j+15])
                    u64 Pm = pk2(0.f, bitf(wd, 15));            // P[0]
                    u64 Pc = pk2(bitf(wd, 0), bitf(wd, 16));    // P[1]
#pragma unroll
                    for (int k = 0; k < 16; k++) {
                        u64 Pn = (k < 15) ? pk2(bitf(wd, k + 1), bitf(wd, k + 17))
                                          : pk2(bitf(wd, 16), 0.f);   // P[k+2]
                        ffma2(O[k], wa2, Pm);
                        ffma2(O[k], wb2, Pc);
                        ffma2(O[k], wc2, Pn);
                        Pm = Pc; Pc = Pn;
                    }
                }
            }
            // store B: fp16 pairs (ch lo, ch hi), permuted layout, STS.128
#pragma unroll
            for (int j = 0; j < 8; j++) {
                float a0, a16, a8, a24, c0, c16, c8, c24;
                upk2(a0, a16, O0[j]);
                upk2(a8, a24, O0[j + 8]);
                upk2(c0, c16, O1[j]);
                upk2(c8, c24, O1[j + 8]);
                uint4 v;
                v.x = packh2(a0,  c0);
                v.y = packh2(a8,  c8);
                v.z = packh2(a16, c16);
                v.w = packh2(a24, c24);
                *reinterpret_cast<uint4*>(bst + j * 16) = v;
            }
        };

        uint32_t sw[6];
        ldspk(t0, sw);

        int it = 0;
        for (int t = t0; t < NTILES; t += GRID, ++it) {
            const int b = it & 1;
            if (it >= 2) BAR_SYNC(3 + b);         // wait B[b] empty
            dwcomp(sw, b ? bst1 : bst0);
            BAR_ARRIVE(1 + b);                    // signal B[b] full
            if (t + GRID < NTILES) ldspk(t + GRID, sw);
        }
    }
}

// ---------------------------------------------------------------------------
// Launcher
// ---------------------------------------------------------------------------
extern "C" void kernel_launch(void* const* d_in, const int* in_sizes, int n_in,
                              void* d_out, int out_size)
{
    const float* x     = (const float*)d_in[0];
    const float* dw_w  = (const float*)d_in[1];
    const float* dw_b  = (const float*)d_in[2];
    const float* pw_w  = (const float*)d_in[3];
    const float* pw_b  = (const float*)d_in[4];
    const float* gamma = (const float*)d_in[5];
    const float* beta  = (const float*)d_in[6];
    const float* rmean = (const float*)d_in[7];
    const float* rvar  = (const float*)d_in[8];
    float* out = (float*)d_out;

    lif_kernel<<<ELEMS_T / (256 * 4), 256>>>(x);

    cudaFuncSetAttribute(fused_ws_kernel,
                         cudaFuncAttributeMaxDynamicSharedMemorySize, SMEM_TOTAL);
    fused_ws_kernel<<<GRID, NTHREADS, SMEM_TOTAL>>>(dw_w, dw_b, pw_w, pw_b,
                                                    gamma, beta, rmean, rvar, out);
}